// round 2
// baseline (speedup 1.0000x reference)
#include <cuda_runtime.h>
#include <math.h>

#define NN 20000
#define NE 320000
#define NB 128
#define H  32
#define AF 64
#define BF 16
#define KP 1088   // 1024 (outer product) + 32 (hsum) + 32 (zero pad) -> 17 K-tiles of 64

// ---------------- device scratch (no allocations allowed) ----------------
__device__ float g_h[3][NN * H];     // node states: h0, h1, h2
__device__ float g_t[NE * H];        // per-edge t = relu(h_bond @ W_e1 + b_e1)  (layer-invariant)
__device__ float g_P[(long)NN * KP]; // per-dst accumulated outer product (+hsum, +pad)
__device__ float g_m[NN * H];        // relu'd aggregated messages (GRU input)
__device__ float g_W2[KP * H];       // rearranged W_e2 with bias rows appended, zero pad
__device__ float g_inv[NN];          // 1/max(deg,1)
__device__ int   g_deg[NN];
__device__ int   g_rp[NN + 1];
__device__ int   g_cur[NN];
__device__ int   g_eids[NE];         // edge ids bucketed by dst (sorted within bucket)

// ---------------- CSR build ----------------
__global__ void k_zero_deg() {
    int i = blockIdx.x * blockDim.x + threadIdx.x;
    if (i < NN) g_deg[i] = 0;
}

__global__ void k_hist(const int* __restrict__ dst) {
    int e = blockIdx.x * blockDim.x + threadIdx.x;
    if (e < NE) atomicAdd(&g_deg[dst[e]], 1);
}

__global__ void k_scan() {
    __shared__ int ws[32];
    __shared__ int carry;
    int tid = threadIdx.x, lane = tid & 31, w = tid >> 5;
    if (tid == 0) carry = 0;
    __syncthreads();
    for (int base = 0; base < NN; base += 1024) {
        int i = base + tid;
        int v = (i < NN) ? g_deg[i] : 0;
        int incl = v;
        #pragma unroll
        for (int off = 1; off < 32; off <<= 1) {
            int t = __shfl_up_sync(0xffffffffu, incl, off);
            if (lane >= off) incl += t;
        }
        if (lane == 31) ws[w] = incl;
        __syncthreads();
        if (w == 0) {
            int wv = ws[lane];
            int wi = wv;
            #pragma unroll
            for (int off = 1; off < 32; off <<= 1) {
                int t = __shfl_up_sync(0xffffffffu, wi, off);
                if (lane >= off) wi += t;
            }
            ws[lane] = wi - wv;  // exclusive warp offset
        }
        __syncthreads();
        int excl = carry + ws[w] + incl - v;
        if (i < NN) {
            g_rp[i]  = excl;
            g_cur[i] = excl;
            g_inv[i] = 1.0f / fmaxf((float)v, 1.0f);
        }
        __syncthreads();  // everyone done reading carry/ws
        if (tid == 1023) carry += ws[31] + incl;
        __syncthreads();
    }
    if (threadIdx.x == 0) g_rp[NN] = carry;
}

__global__ void k_scatter(const int* __restrict__ dst) {
    int e = blockIdx.x * blockDim.x + threadIdx.x;
    if (e < NE) {
        int pos = atomicAdd(&g_cur[dst[e]], 1);
        g_eids[pos] = e;
    }
}

// sort each dst bucket by edge id -> deterministic fp accumulation order
__global__ void k_sort() {
    __shared__ int buf[8][128];
    int w = threadIdx.x >> 5, lane = threadIdx.x & 31;
    int d = blockIdx.x * 8 + w;
    int beg = g_rp[d], end = g_rp[d + 1];
    int cnt = end - beg;
    if (cnt > 128) cnt = 128;  // never happens for Poisson(16)
    for (int p = lane; p < cnt; p += 32) buf[w][p] = g_eids[beg + p];
    __syncwarp();
    for (int i = 0; i < cnt - 1; i++) {
        int bv = 0x7fffffff, bp = i;
        for (int p = i + lane; p < cnt; p += 32) {
            int v = buf[w][p];
            if (v < bv) { bv = v; bp = p; }
        }
        #pragma unroll
        for (int off = 16; off; off >>= 1) {
            int ov = __shfl_down_sync(0xffffffffu, bv, off);
            int op = __shfl_down_sync(0xffffffffu, bp, off);
            if (ov < bv) { bv = ov; bp = op; }
        }
        bv = __shfl_sync(0xffffffffu, bv, 0);
        bp = __shfl_sync(0xffffffffu, bp, 0);
        if (lane == 0) { int t = buf[w][i]; buf[w][i] = bv; buf[w][bp] = t; }
        __syncwarp();
    }
    for (int p = lane; p < cnt; p += 32) g_eids[beg + p] = buf[w][p];
}

// ---------------- weight prep: W2[kk][o] with kk=(k*32+i) -> W_e2[k, i*32+o]; rows 1024..1055 = b_e2; rest 0
__global__ void k_w2(const float* __restrict__ W_e2, const float* __restrict__ b_e2) {
    int idx = blockIdx.x * blockDim.x + threadIdx.x;
    if (idx >= KP * H) return;
    int kk = idx >> 5, o = idx & 31;
    float v;
    if (kk < 1024)      v = W_e2[(kk >> 5) * 1024 + (kk & 31) * 32 + o];
    else if (kk < 1056) v = b_e2[(kk - 1024) * 32 + o];
    else                v = 0.0f;
    g_W2[idx] = v;
}

// ---------------- atom embedding: h0 = n_feat @ W_atom + b_atom ----------------
__global__ void k_h0(const float* __restrict__ nf, const float* __restrict__ Wa,
                     const float* __restrict__ ba) {
    __shared__ float Ws[AF * H];
    __shared__ float bs[H];
    for (int i = threadIdx.x; i < AF * H; i += 256) Ws[i] = Wa[i];
    if (threadIdx.x < H) bs[threadIdx.x] = ba[threadIdx.x];
    __syncthreads();
    int n = blockIdx.x * 8 + (threadIdx.x >> 5);
    int c = threadIdx.x & 31;
    const float* row = nf + n * AF;
    float acc = bs[c];
    #pragma unroll
    for (int f = 0; f < AF; f++) acc += __ldg(row + f) * Ws[f * H + c];
    g_h[0][n * H + c] = acc;
}

// ---------------- edge network front half: t = relu((e_feat@W_bond+b_bond)@W_e1+b_e1) ----------------
__global__ void k_t(const float* __restrict__ ef, const float* __restrict__ Wb,
                    const float* __restrict__ bb, const float* __restrict__ We1,
                    const float* __restrict__ be1) {
    __shared__ float Wbs[BF * H], We1s[H * H], bbs[H], be1s[H];
    for (int i = threadIdx.x; i < BF * H; i += 256) Wbs[i] = Wb[i];
    for (int i = threadIdx.x; i < H * H; i += 256) We1s[i] = We1[i];
    if (threadIdx.x < H) { bbs[threadIdx.x] = bb[threadIdx.x]; be1s[threadIdx.x] = be1[threadIdx.x]; }
    __syncthreads();
    int w = blockIdx.x * 8 + (threadIdx.x >> 5);
    int c = threadIdx.x & 31;
    for (int e = w; e < NE; e += 20000) {
        const float* er = ef + e * BF;
        float hb = bbs[c];
        #pragma unroll
        for (int f = 0; f < BF; f++) hb += __ldg(er + f) * Wbs[f * H + c];
        float acc = be1s[c];
        #pragma unroll
        for (int j = 0; j < H; j++) {
            float hbj = __shfl_sync(0xffffffffu, hb, j);
            acc += hbj * We1s[j * H + c];
        }
        g_t[e * H + c] = fmaxf(acc, 0.0f);
    }
}

// ---------------- per-dst accumulated outer product: P[d,k,i] = sum_{e->d} t_e[k]*h[src_e][i] ----------------
__global__ void k_accum(int hs, const int* __restrict__ src) {
    const float* __restrict__ h = g_h[hs];
    int d = blockIdx.x * 8 + (threadIdx.x >> 5);
    int lane = threadIdx.x & 31;
    int beg = g_rp[d], end = g_rp[d + 1];
    float acc[H];
    #pragma unroll
    for (int k = 0; k < H; k++) acc[k] = 0.0f;
    float hsum = 0.0f;
    for (int p = beg; p < end; p++) {
        int e = g_eids[p];
        int s = src[e];
        float hv = h[s * H + lane];
        hsum += hv;
        const float4* t4 = (const float4*)(g_t + e * H);
        #pragma unroll
        for (int q = 0; q < 8; q++) {
            float4 tv = t4[q];
            acc[q * 4 + 0] += tv.x * hv;
            acc[q * 4 + 1] += tv.y * hv;
            acc[q * 4 + 2] += tv.z * hv;
            acc[q * 4 + 3] += tv.w * hv;
        }
    }
    float* Pr = g_P + (long)d * KP;
    #pragma unroll
    for (int k = 0; k < H; k++) Pr[k * H + lane] = acc[k];
    Pr[1024 + lane] = hsum;
    Pr[1056 + lane] = 0.0f;
}

// ---------------- agg GEMM + inv_deg + relu: m = relu((P @ W2) * inv_deg) ----------------
__global__ void k_gemm() {
    __shared__ float As[64][68];   // pad 68: conflict-free, float4-aligned
    __shared__ float Bs[64][32];
    int tid = threadIdx.x;
    int tx = tid & 15, ty = tid >> 4;      // tx: col pair, ty: row group
    int nb = blockIdx.x * 64;
    float acc[4][2];
    #pragma unroll
    for (int j = 0; j < 4; j++) { acc[j][0] = 0.0f; acc[j][1] = 0.0f; }
    int lr = tid >> 2;         // load row 0..63 (4 threads per row)
    int lq = tid & 3;

    for (int kb = 0; kb < KP; kb += 64) {
        int node = nb + lr;
        const float* Pp = g_P + (long)node * KP + kb + lq * 16;
        #pragma unroll
        for (int q = 0; q < 4; q++) {
            float4 v = (node < NN) ? *((const float4*)(Pp + q * 4)) : make_float4(0, 0, 0, 0);
            *((float4*)&As[lr][lq * 16 + q * 4]) = v;
        }
        const float* Wp = g_W2 + (kb + lr) * H + lq * 8;
        #pragma unroll
        for (int q = 0; q < 2; q++) {
            *((float4*)&Bs[lr][lq * 8 + q * 4]) = *((const float4*)(Wp + q * 4));
        }
        __syncthreads();
        #pragma unroll 16
        for (int kk = 0; kk < 64; kk++) {
            float2 b = *((const float2*)&Bs[kk][2 * tx]);
            #pragma unroll
            for (int j = 0; j < 4; j++) {
                float a = As[ty + j * 16][kk];
                acc[j][0] += a * b.x;
                acc[j][1] += a * b.y;
            }
        }
        __syncthreads();
    }
    #pragma unroll
    for (int j = 0; j < 4; j++) {
        int node = nb + ty + j * 16;
        if (node < NN) {
            float iv = g_inv[node];
            g_m[node * H + 2 * tx]     = fmaxf(acc[j][0] * iv, 0.0f);
            g_m[node * H + 2 * tx + 1] = fmaxf(acc[j][1] * iv, 0.0f);
        }
    }
}

// ---------------- GRU cell ----------------
__global__ void k_gru(int hin, int hout,
                      const float* __restrict__ Wih, const float* __restrict__ Whh,
                      const float* __restrict__ bih, const float* __restrict__ bhh) {
    __shared__ float Wis[96 * 33], Whs[96 * 33];
    __shared__ float bis[96], bhs[96];
    for (int i = threadIdx.x; i < 96 * 32; i += 256) {
        int r = i >> 5, cc = i & 31;
        Wis[r * 33 + cc] = Wih[i];
        Whs[r * 33 + cc] = Whh[i];
    }
    if (threadIdx.x < 96) { bis[threadIdx.x] = bih[threadIdx.x]; bhs[threadIdx.x] = bhh[threadIdx.x]; }
    __syncthreads();
    int n = blockIdx.x * 8 + (threadIdx.x >> 5);
    int c = threadIdx.x & 31;
    float mv = g_m[n * H + c];
    float hv = g_h[hin][n * H + c];
    float gi0 = bis[c], gi1 = bis[c + 32], gi2 = bis[c + 64];
    float gh0 = bhs[c], gh1 = bhs[c + 32], gh2 = bhs[c + 64];
    #pragma unroll
    for (int j = 0; j < H; j++) {
        float mj = __shfl_sync(0xffffffffu, mv, j);
        float hj = __shfl_sync(0xffffffffu, hv, j);
        gi0 += mj * Wis[c * 33 + j];
        gi1 += mj * Wis[(c + 32) * 33 + j];
        gi2 += mj * Wis[(c + 64) * 33 + j];
        gh0 += hj * Whs[c * 33 + j];
        gh1 += hj * Whs[(c + 32) * 33 + j];
        gh2 += hj * Whs[(c + 64) * 33 + j];
    }
    float r = 1.0f / (1.0f + __expf(-(gi0 + gh0)));
    float z = 1.0f / (1.0f + __expf(-(gi1 + gh1)));
    float nn = tanhf(gi2 + r * gh2);
    g_h[hout][n * H + c] = (1.0f - z) * nn + z * hv;
}

// ---------------- per-graph mean readout ----------------
__device__ __forceinline__ int lbound(const int* a, int n, int key) {
    int lo = 0, hi = n;
    while (lo < hi) { int mid = (lo + hi) >> 1; if (a[mid] < key) lo = mid + 1; else hi = mid; }
    return lo;
}

__global__ void k_readout(int hs, const int* __restrict__ gid, float* __restrict__ out) {
    __shared__ float red[4][32];
    int b = blockIdx.x;
    int lo = lbound(gid, NN, b), hi = lbound(gid, NN, b + 1);
    int w = threadIdx.x >> 5, lane = threadIdx.x & 31;
    const float* h = g_h[hs];
    float s = 0.0f;
    for (int n = lo + w; n < hi; n += 4) s += h[n * H + lane];
    red[w][lane] = s;
    __syncthreads();
    if (w == 0) {
        float tot = red[0][lane] + red[1][lane] + red[2][lane] + red[3][lane];
        out[b * H + lane] = tot / fmaxf((float)(hi - lo), 1.0f);
    }
}

// ---------------- launcher ----------------
extern "C" void kernel_launch(void* const* d_in, const int* in_sizes, int n_in,
                              void* d_out, int out_size) {
    const float* n_feat = (const float*)d_in[0];
    const float* e_feat = (const float*)d_in[1];
    const int*   src    = (const int*)d_in[2];
    const int*   dst    = (const int*)d_in[3];
    const int*   gid    = (const int*)d_in[4];
    const float* W_atom = (const float*)d_in[5];
    const float* b_atom = (const float*)d_in[6];
    const float* W_bond = (const float*)d_in[7];
    const float* b_bond = (const float*)d_in[8];
    const float* W_e1   = (const float*)d_in[9];
    const float* b_e1   = (const float*)d_in[10];
    const float* W_e2   = (const float*)d_in[11];
    const float* b_e2   = (const float*)d_in[12];
    const float* W_ih   = (const float*)d_in[13];
    const float* W_hh   = (const float*)d_in[14];
    const float* b_ih   = (const float*)d_in[15];
    const float* b_hh   = (const float*)d_in[16];
    float* out = (float*)d_out;

    k_zero_deg<<<(NN + 255) / 256, 256>>>();
    k_hist<<<NE / 256, 256>>>(dst);
    k_scan<<<1, 1024>>>();
    k_scatter<<<NE / 256, 256>>>(dst);
    k_sort<<<NN / 8, 256>>>();
    k_w2<<<(KP * H) / 256, 256>>>(W_e2, b_e2);
    k_h0<<<NN / 8, 256>>>(n_feat, W_atom, b_atom);
    k_t<<<2500, 256>>>(e_feat, W_bond, b_bond, W_e1, b_e1);

    for (int l = 0; l < 2; l++) {
        k_accum<<<NN / 8, 256>>>(l, src);
        k_gemm<<<(NN + 63) / 64, 256>>>();
        k_gru<<<NN / 8, 256>>>(l, l + 1, W_ih, W_hh, b_ih, b_hh);
    }
    k_readout<<<NB, 128>>>(2, gid, out);
}

// round 3
// speedup vs baseline: 1.2006x; 1.2006x over previous
#include <cuda_runtime.h>
#include <math.h>

#define NN 20000
#define NE 320000
#define NB 128
#define H  32
#define AF 64
#define BF 16
#define KP 1088   // 1024 (outer product) + 32 (hsum) + 32 (zero pad)
#define BM 144    // gemm node-tile: ceil(20000/144)=139 blocks < 148 SMs -> single wave

typedef unsigned long long ull;

// packed fp32x2 ops (sm_103a FFMA2 path)
#define PK2(d, x, y)     asm("mov.b64 %0, {%1, %2};" : "=l"(d) : "f"(x), "f"(y))
#define UPK2(x, y, d)    asm("mov.b64 {%0, %1}, %2;" : "=f"(x), "=f"(y) : "l"(d))
#define FMA2(d, a, b, c) asm("fma.rn.f32x2 %0, %1, %2, %3;" : "=l"(d) : "l"(a), "l"(b), "l"(c))

// ---------------- device scratch ----------------
__device__ float g_h[3][NN * H];
__device__ float g_t[NE * H];
__device__ float g_P[(long)NN * KP];
__device__ float g_m[NN * H];
__device__ float g_W2[KP * H];
__device__ float g_inv[NN];
__device__ int   g_deg[NN];
__device__ int   g_rp[NN + 1];
__device__ int   g_cur[NN];
__device__ int   g_eids[NE];

// ---------------- CSR build ----------------
__global__ void k_zero_deg() {
    int i = blockIdx.x * blockDim.x + threadIdx.x;
    if (i < NN) g_deg[i] = 0;
}

__global__ void k_hist(const int* __restrict__ dst) {
    int e = blockIdx.x * blockDim.x + threadIdx.x;
    if (e < NE) atomicAdd(&g_deg[dst[e]], 1);
}

__global__ void k_scan() {
    __shared__ int ws[32];
    __shared__ int carry;
    int tid = threadIdx.x, lane = tid & 31, w = tid >> 5;
    if (tid == 0) carry = 0;
    __syncthreads();
    for (int base = 0; base < NN; base += 1024) {
        int i = base + tid;
        int v = (i < NN) ? g_deg[i] : 0;
        int incl = v;
        #pragma unroll
        for (int off = 1; off < 32; off <<= 1) {
            int t = __shfl_up_sync(0xffffffffu, incl, off);
            if (lane >= off) incl += t;
        }
        if (lane == 31) ws[w] = incl;
        __syncthreads();
        if (w == 0) {
            int wv = ws[lane];
            int wi = wv;
            #pragma unroll
            for (int off = 1; off < 32; off <<= 1) {
                int t = __shfl_up_sync(0xffffffffu, wi, off);
                if (lane >= off) wi += t;
            }
            ws[lane] = wi - wv;
        }
        __syncthreads();
        int excl = carry + ws[w] + incl - v;
        if (i < NN) {
            g_rp[i]  = excl;
            g_cur[i] = excl;
            g_inv[i] = 1.0f / fmaxf((float)v, 1.0f);
        }
        __syncthreads();
        if (tid == 1023) carry += ws[31] + incl;
        __syncthreads();
    }
    if (threadIdx.x == 0) g_rp[NN] = carry;
}

__global__ void k_scatter(const int* __restrict__ dst) {
    int e = blockIdx.x * blockDim.x + threadIdx.x;
    if (e < NE) {
        int pos = atomicAdd(&g_cur[dst[e]], 1);
        g_eids[pos] = e;
    }
}

// sort each dst bucket by edge id -> deterministic fp accumulation order
__global__ void k_sort() {
    __shared__ int buf[8][128];
    int w = threadIdx.x >> 5, lane = threadIdx.x & 31;
    int d = blockIdx.x * 8 + w;
    int beg = g_rp[d], end = g_rp[d + 1];
    int cnt = end - beg;
    if (cnt > 128) cnt = 128;
    for (int p = lane; p < cnt; p += 32) buf[w][p] = g_eids[beg + p];
    __syncwarp();
    for (int i = 0; i < cnt - 1; i++) {
        int bv = 0x7fffffff, bp = i;
        for (int p = i + lane; p < cnt; p += 32) {
            int v = buf[w][p];
            if (v < bv) { bv = v; bp = p; }
        }
        #pragma unroll
        for (int off = 16; off; off >>= 1) {
            int ov = __shfl_down_sync(0xffffffffu, bv, off);
            int op = __shfl_down_sync(0xffffffffu, bp, off);
            if (ov < bv) { bv = ov; bp = op; }
        }
        bv = __shfl_sync(0xffffffffu, bv, 0);
        bp = __shfl_sync(0xffffffffu, bp, 0);
        if (lane == 0) { int t = buf[w][i]; buf[w][i] = bv; buf[w][bp] = t; }
        __syncwarp();
    }
    for (int p = lane; p < cnt; p += 32) g_eids[beg + p] = buf[w][p];
}

// ---------------- weight prep ----------------
__global__ void k_w2(const float* __restrict__ W_e2, const float* __restrict__ b_e2) {
    int idx = blockIdx.x * blockDim.x + threadIdx.x;
    if (idx >= KP * H) return;
    int kk = idx >> 5, o = idx & 31;
    float v;
    if (kk < 1024)      v = W_e2[(kk >> 5) * 1024 + (kk & 31) * 32 + o];
    else if (kk < 1056) v = b_e2[(kk - 1024) * 32 + o];
    else                v = 0.0f;
    g_W2[idx] = v;
}

// ---------------- atom embedding ----------------
__global__ void k_h0(const float* __restrict__ nf, const float* __restrict__ Wa,
                     const float* __restrict__ ba) {
    __shared__ float Ws[AF * H];
    __shared__ float bs[H];
    for (int i = threadIdx.x; i < AF * H; i += 256) Ws[i] = Wa[i];
    if (threadIdx.x < H) bs[threadIdx.x] = ba[threadIdx.x];
    __syncthreads();
    int n = blockIdx.x * 8 + (threadIdx.x >> 5);
    int c = threadIdx.x & 31;
    const float* row = nf + n * AF;
    float acc = bs[c];
    #pragma unroll
    for (int f = 0; f < AF; f++) acc += __ldg(row + f) * Ws[f * H + c];
    g_h[0][n * H + c] = acc;
}

// ---------------- edge net front half: t = relu((e_feat@W_bond+b_bond)@W_e1+b_e1) ----------------
__global__ void __launch_bounds__(256) k_t(const float* __restrict__ ef, const float* __restrict__ Wb,
                    const float* __restrict__ bb, const float* __restrict__ We1,
                    const float* __restrict__ be1) {
    int lane = threadIdx.x & 31;
    float wbr[BF], w1r[H];
    #pragma unroll
    for (int f = 0; f < BF; f++) wbr[f] = Wb[f * H + lane];
    #pragma unroll
    for (int j = 0; j < H; j++) w1r[j] = We1[j * H + lane];
    float bbv = bb[lane], b1v = be1[lane];
    int w = blockIdx.x * 8 + (threadIdx.x >> 5);
    for (int e = w; e < NE; e += 20000) {
        const float4* er = (const float4*)(ef + e * BF);
        float4 e0 = er[0], e1 = er[1], e2 = er[2], e3 = er[3];
        float hb = bbv;
        hb += e0.x * wbr[0]  + e0.y * wbr[1]  + e0.z * wbr[2]  + e0.w * wbr[3];
        hb += e1.x * wbr[4]  + e1.y * wbr[5]  + e1.z * wbr[6]  + e1.w * wbr[7];
        hb += e2.x * wbr[8]  + e2.y * wbr[9]  + e2.z * wbr[10] + e2.w * wbr[11];
        hb += e3.x * wbr[12] + e3.y * wbr[13] + e3.z * wbr[14] + e3.w * wbr[15];
        float a0 = b1v, a1 = 0.0f;
        #pragma unroll
        for (int j = 0; j < H; j += 2) {
            a0 += __shfl_sync(0xffffffffu, hb, j)     * w1r[j];
            a1 += __shfl_sync(0xffffffffu, hb, j + 1) * w1r[j + 1];
        }
        g_t[e * H + lane] = fmaxf(a0 + a1, 0.0f);
    }
}

// ---------------- per-dst accumulated outer product ----------------
__global__ void __launch_bounds__(256) k_accum(int hs, const int* __restrict__ src) {
    const float* __restrict__ h = g_h[hs];
    int d = blockIdx.x * 8 + (threadIdx.x >> 5);
    int lane = threadIdx.x & 31;
    int beg = g_rp[d], end = g_rp[d + 1];
    ull acc2[16];
    #pragma unroll
    for (int q = 0; q < 16; q++) acc2[q] = 0ull;
    float hsum = 0.0f;
    for (int base = beg; base < end; base += 32) {
        int rem = end - base; if (rem > 32) rem = 32;
        int e_l = 0, s_l = 0;
        if (lane < rem) { e_l = __ldg(&g_eids[base + lane]); s_l = __ldg(&src[e_l]); }
        for (int p = 0; p < rem; p++) {
            int e = __shfl_sync(0xffffffffu, e_l, p);
            int s = __shfl_sync(0xffffffffu, s_l, p);
            float hv = h[s * H + lane];
            const float4* t4 = (const float4*)(g_t + e * H);
            float4 ta = t4[0], tb = t4[1], tc = t4[2], td = t4[3];
            float4 te = t4[4], tf = t4[5], tg = t4[6], th = t4[7];
            hsum += hv;
            ull h2; PK2(h2, hv, hv);
            ull tp;
            PK2(tp, ta.x, ta.y); FMA2(acc2[0],  tp, h2, acc2[0]);
            PK2(tp, ta.z, ta.w); FMA2(acc2[1],  tp, h2, acc2[1]);
            PK2(tp, tb.x, tb.y); FMA2(acc2[2],  tp, h2, acc2[2]);
            PK2(tp, tb.z, tb.w); FMA2(acc2[3],  tp, h2, acc2[3]);
            PK2(tp, tc.x, tc.y); FMA2(acc2[4],  tp, h2, acc2[4]);
            PK2(tp, tc.z, tc.w); FMA2(acc2[5],  tp, h2, acc2[5]);
            PK2(tp, td.x, td.y); FMA2(acc2[6],  tp, h2, acc2[6]);
            PK2(tp, td.z, td.w); FMA2(acc2[7],  tp, h2, acc2[7]);
            PK2(tp, te.x, te.y); FMA2(acc2[8],  tp, h2, acc2[8]);
            PK2(tp, te.z, te.w); FMA2(acc2[9],  tp, h2, acc2[9]);
            PK2(tp, tf.x, tf.y); FMA2(acc2[10], tp, h2, acc2[10]);
            PK2(tp, tf.z, tf.w); FMA2(acc2[11], tp, h2, acc2[11]);
            PK2(tp, tg.x, tg.y); FMA2(acc2[12], tp, h2, acc2[12]);
            PK2(tp, tg.z, tg.w); FMA2(acc2[13], tp, h2, acc2[13]);
            PK2(tp, th.x, th.y); FMA2(acc2[14], tp, h2, acc2[14]);
            PK2(tp, th.z, th.w); FMA2(acc2[15], tp, h2, acc2[15]);
        }
    }
    float* Pr = g_P + (long)d * KP;
    #pragma unroll
    for (int q = 0; q < 16; q++) {
        float x, y; UPK2(x, y, acc2[q]);
        Pr[(2 * q) * H + lane]     = x;
        Pr[(2 * q + 1) * H + lane] = y;
    }
    Pr[1024 + lane] = hsum;
    Pr[1056 + lane] = 0.0f;
}

// ---------------- agg GEMM: m = relu((P @ W2) * inv_deg) ----------------
__device__ __forceinline__ void gemm_load(int kb, int tid, int nb,
                                          float4* va, float4& wb0, float4& wb1) {
    #pragma unroll
    for (int i = 0; i < 8; i++) {
        int idx = i * 288 + tid;
        int node = idx >> 4, q = idx & 15;
        int gn = nb + node;
        if (gn < NN) va[i] = *(const float4*)(g_P + (long)gn * KP + kb + 4 * q);
        else         va[i] = make_float4(0.f, 0.f, 0.f, 0.f);
    }
    {
        int r = tid >> 3, c = (tid & 7) * 4;
        wb0 = *(const float4*)(g_W2 + (kb + r) * H + c);
    }
    if (tid < 224) {
        int idx = tid + 288;
        int r = idx >> 3, c = (idx & 7) * 4;
        wb1 = *(const float4*)(g_W2 + (kb + r) * H + c);
    }
}

__global__ void __launch_bounds__(288) k_gemm() {
    __shared__ float AsT[64][160];  // K-major A, XOR-swizzled node index
    __shared__ float Bs[64][32];
    int tid = threadIdx.x;
    int nb = blockIdx.x * BM;
    int tx = tid & 7, ty = tid >> 3;   // outs 4*tx.., nodes 4*ty..
    ull acc[4][2];
    #pragma unroll
    for (int n = 0; n < 4; n++) { acc[n][0] = 0ull; acc[n][1] = 0ull; }

    float4 va[8];
    float4 wb0 = make_float4(0.f, 0.f, 0.f, 0.f), wb1 = wb0;
    gemm_load(0, tid, nb, va, wb0, wb1);

    #pragma unroll 1
    for (int t = 0; t < 17; t++) {
        __syncthreads();
        // store staged tile (transpose A with swizzle)
        #pragma unroll
        for (int i = 0; i < 8; i++) {
            int idx = i * 288 + tid;
            int node = idx >> 4, q = idx & 15;
            int col = node ^ ((q & 7) << 2);
            AsT[4 * q + 0][col] = va[i].x;
            AsT[4 * q + 1][col] = va[i].y;
            AsT[4 * q + 2][col] = va[i].z;
            AsT[4 * q + 3][col] = va[i].w;
        }
        { int r = tid >> 3, c = (tid & 7) * 4; *(float4*)&Bs[r][c] = wb0; }
        if (tid < 224) { int idx = tid + 288; int r = idx >> 3, c = (idx & 7) * 4; *(float4*)&Bs[r][c] = wb1; }
        __syncthreads();
        if (t < 16) gemm_load((t + 1) * 64, tid, nb, va, wb0, wb1);
        #pragma unroll 16
        for (int kk = 0; kk < 64; kk++) {
            float4 a4 = *(const float4*)&AsT[kk][(4 * ty) ^ (((kk >> 2) & 7) << 2)];
            float4 b4 = *(const float4*)&Bs[kk][4 * tx];
            ull b01, b23, aa;
            PK2(b01, b4.x, b4.y); PK2(b23, b4.z, b4.w);
            PK2(aa, a4.x, a4.x); FMA2(acc[0][0], aa, b01, acc[0][0]); FMA2(acc[0][1], aa, b23, acc[0][1]);
            PK2(aa, a4.y, a4.y); FMA2(acc[1][0], aa, b01, acc[1][0]); FMA2(acc[1][1], aa, b23, acc[1][1]);
            PK2(aa, a4.z, a4.z); FMA2(acc[2][0], aa, b01, acc[2][0]); FMA2(acc[2][1], aa, b23, acc[2][1]);
            PK2(aa, a4.w, a4.w); FMA2(acc[3][0], aa, b01, acc[3][0]); FMA2(acc[3][1], aa, b23, acc[3][1]);
        }
    }
    #pragma unroll
    for (int n = 0; n < 4; n++) {
        int node = nb + 4 * ty + n;
        if (node < NN) {
            float iv = g_inv[node];
            float x0, x1, x2, x3;
            UPK2(x0, x1, acc[n][0]);
            UPK2(x2, x3, acc[n][1]);
            float4 o;
            o.x = fmaxf(x0 * iv, 0.0f);
            o.y = fmaxf(x1 * iv, 0.0f);
            o.z = fmaxf(x2 * iv, 0.0f);
            o.w = fmaxf(x3 * iv, 0.0f);
            *(float4*)(g_m + node * H + 4 * tx) = o;
        }
    }
}

// ---------------- GRU cell ----------------
__global__ void k_gru(int hin, int hout,
                      const float* __restrict__ Wih, const float* __restrict__ Whh,
                      const float* __restrict__ bih, const float* __restrict__ bhh) {
    __shared__ float Wis[96 * 33], Whs[96 * 33];
    __shared__ float bis[96], bhs[96];
    for (int i = threadIdx.x; i < 96 * 32; i += 256) {
        int r = i >> 5, cc = i & 31;
        Wis[r * 33 + cc] = Wih[i];
        Whs[r * 33 + cc] = Whh[i];
    }
    if (threadIdx.x < 96) { bis[threadIdx.x] = bih[threadIdx.x]; bhs[threadIdx.x] = bhh[threadIdx.x]; }
    __syncthreads();
    int n = blockIdx.x * 8 + (threadIdx.x >> 5);
    int c = threadIdx.x & 31;
    float mv = g_m[n * H + c];
    float hv = g_h[hin][n * H + c];
    float gi0 = bis[c], gi1 = bis[c + 32], gi2 = bis[c + 64];
    float gh0 = bhs[c], gh1 = bhs[c + 32], gh2 = bhs[c + 64];
    #pragma unroll
    for (int j = 0; j < H; j++) {
        float mj = __shfl_sync(0xffffffffu, mv, j);
        float hj = __shfl_sync(0xffffffffu, hv, j);
        gi0 += mj * Wis[c * 33 + j];
        gi1 += mj * Wis[(c + 32) * 33 + j];
        gi2 += mj * Wis[(c + 64) * 33 + j];
        gh0 += hj * Whs[c * 33 + j];
        gh1 += hj * Whs[(c + 32) * 33 + j];
        gh2 += hj * Whs[(c + 64) * 33 + j];
    }
    float r = 1.0f / (1.0f + __expf(-(gi0 + gh0)));
    float z = 1.0f / (1.0f + __expf(-(gi1 + gh1)));
    float nn = tanhf(gi2 + r * gh2);
    g_h[hout][n * H + c] = (1.0f - z) * nn + z * hv;
}

// ---------------- per-graph mean readout ----------------
__device__ __forceinline__ int lbound(const int* a, int n, int key) {
    int lo = 0, hi = n;
    while (lo < hi) { int mid = (lo + hi) >> 1; if (a[mid] < key) lo = mid + 1; else hi = mid; }
    return lo;
}

__global__ void k_readout(int hs, const int* __restrict__ gid, float* __restrict__ out) {
    __shared__ float red[4][32];
    int b = blockIdx.x;
    int lo = lbound(gid, NN, b), hi = lbound(gid, NN, b + 1);
    int w = threadIdx.x >> 5, lane = threadIdx.x & 31;
    const float* h = g_h[hs];
    float s = 0.0f;
    for (int n = lo + w; n < hi; n += 4) s += h[n * H + lane];
    red[w][lane] = s;
    __syncthreads();
    if (w == 0) {
        float tot = red[0][lane] + red[1][lane] + red[2][lane] + red[3][lane];
        out[b * H + lane] = tot / fmaxf((float)(hi - lo), 1.0f);
    }
}

// ---------------- launcher ----------------
extern "C" void kernel_launch(void* const* d_in, const int* in_sizes, int n_in,
                              void* d_out, int out_size) {
    const float* n_feat = (const float*)d_in[0];
    const float* e_feat = (const float*)d_in[1];
    const int*   src    = (const int*)d_in[2];
    const int*   dst    = (const int*)d_in[3];
    const int*   gid    = (const int*)d_in[4];
    const float* W_atom = (const float*)d_in[5];
    const float* b_atom = (const float*)d_in[6];
    const float* W_bond = (const float*)d_in[7];
    const float* b_bond = (const float*)d_in[8];
    const float* W_e1   = (const float*)d_in[9];
    const float* b_e1   = (const float*)d_in[10];
    const float* W_e2   = (const float*)d_in[11];
    const float* b_e2   = (const float*)d_in[12];
    const float* W_ih   = (const float*)d_in[13];
    const float* W_hh   = (const float*)d_in[14];
    const float* b_ih   = (const float*)d_in[15];
    const float* b_hh   = (const float*)d_in[16];
    float* out = (float*)d_out;

    k_zero_deg<<<(NN + 255) / 256, 256>>>();
    k_hist<<<NE / 256, 256>>>(dst);
    k_scan<<<1, 1024>>>();
    k_scatter<<<NE / 256, 256>>>(dst);
    k_sort<<<NN / 8, 256>>>();
    k_w2<<<(KP * H) / 256, 256>>>(W_e2, b_e2);
    k_h0<<<NN / 8, 256>>>(n_feat, W_atom, b_atom);
    k_t<<<2500, 256>>>(e_feat, W_bond, b_bond, W_e1, b_e1);

    for (int l = 0; l < 2; l++) {
        k_accum<<<NN / 8, 256>>>(l, src);
        k_gemm<<<(NN + BM - 1) / BM, 288>>>();
        k_gru<<<NN / 8, 256>>>(l, l + 1, W_ih, W_hh, b_ih, b_hh);
    }
    k_readout<<<NB, 128>>>(2, gid, out);
}

// round 4
// speedup vs baseline: 1.3859x; 1.1544x over previous
#include <cuda_runtime.h>
#include <math.h>

#define NN 20000
#define NE 320000
#define NB 128
#define H  32
#define AF 64
#define BF 16
#define KP 1088   // 1024 (outer product) + 32 (hsum) + 32 (zero pad)
#define BM 144    // gemm node-tile: 139 blocks < 148 SMs -> single wave

typedef unsigned long long ull;

// packed fp32x2 ops (sm_103a FFMA2 path)
#define PK2(d, x, y)     asm("mov.b64 %0, {%1, %2};" : "=l"(d) : "f"(x), "f"(y))
#define UPK2(x, y, d)    asm("mov.b64 {%0, %1}, %2;" : "=f"(x), "=f"(y) : "l"(d))
#define FMA2(d, a, b, c) asm("fma.rn.f32x2 %0, %1, %2, %3;" : "=l"(d) : "l"(a), "l"(b), "l"(c))

// ---------------- device scratch ----------------
__device__ float g_h[3][NN * H];
__device__ float g_t[NE * H];
__device__ float g_P[(long)NN * KP];
__device__ float g_m[NN * H];
__device__ float g_W2[KP * H];
__device__ float g_Wc[BF * H];     // collapsed W_bond @ W_e1
__device__ float g_bc[H];          // collapsed b_bond @ W_e1 + b_e1
__device__ float g_inv[NN];
__device__ int   g_deg[NN];        // static zero-init; re-zeroed by k_scatter each call
__device__ int   g_rp[NN + 1];
__device__ int   g_cur[NN];
__device__ int   g_eids[NE];

// ---------------- hist + edge-net weight collapse ----------------
__global__ void k_hist_prep(const int* __restrict__ dst,
                            const float* __restrict__ Wb, const float* __restrict__ bb,
                            const float* __restrict__ We1, const float* __restrict__ be1) {
    int b = blockIdx.x;
    if (b < 1250) {
        int e = b * 256 + threadIdx.x;
        atomicAdd(&g_deg[dst[e]], 1);
    } else {
        // Wc[f][o] = sum_j Wb[f][j] * We1[j][o]; bc[o] = be1[o] + sum_j bb[j]*We1[j][o]
        int tid = threadIdx.x;
        #pragma unroll
        for (int r = 0; r < 2; r++) {
            int idx = tid + r * 256;
            int f = idx >> 5, o = idx & 31;
            float acc = 0.0f;
            #pragma unroll
            for (int j = 0; j < H; j++) acc += Wb[f * H + j] * We1[j * H + o];
            g_Wc[idx] = acc;
        }
        if (tid < H) {
            float acc = be1[tid];
            #pragma unroll
            for (int j = 0; j < H; j++) acc += bb[j] * We1[j * H + tid];
            g_bc[tid] = acc;
        }
    }
}

// ---------------- scan ----------------
__global__ void k_scan() {
    __shared__ int ws[32];
    __shared__ int carry;
    int tid = threadIdx.x, lane = tid & 31, w = tid >> 5;
    if (tid == 0) carry = 0;
    __syncthreads();
    for (int base = 0; base < NN; base += 1024) {
        int i = base + tid;
        int v = (i < NN) ? g_deg[i] : 0;
        int incl = v;
        #pragma unroll
        for (int off = 1; off < 32; off <<= 1) {
            int t = __shfl_up_sync(0xffffffffu, incl, off);
            if (lane >= off) incl += t;
        }
        if (lane == 31) ws[w] = incl;
        __syncthreads();
        if (w == 0) {
            int wv = ws[lane];
            int wi = wv;
            #pragma unroll
            for (int off = 1; off < 32; off <<= 1) {
                int t = __shfl_up_sync(0xffffffffu, wi, off);
                if (lane >= off) wi += t;
            }
            ws[lane] = wi - wv;
        }
        __syncthreads();
        int excl = carry + ws[w] + incl - v;
        if (i < NN) {
            g_rp[i]  = excl;
            g_cur[i] = excl;
            g_inv[i] = 1.0f / fmaxf((float)v, 1.0f);
        }
        __syncthreads();
        if (tid == 1023) carry += ws[31] + incl;
        __syncthreads();
    }
    if (threadIdx.x == 0) g_rp[NN] = carry;
}

// ---------------- scatter (+ re-zero g_deg for next call) ----------------
__global__ void k_scatter(const int* __restrict__ dst) {
    int e = blockIdx.x * blockDim.x + threadIdx.x;
    int pos = atomicAdd(&g_cur[dst[e]], 1);
    g_eids[pos] = e;
    if (e < NN) g_deg[e] = 0;
}

// ---------------- bucket sort by edge id (deterministic accumulation order) ----------------
__global__ void k_sort() {
    __shared__ int buf[8][128];
    int w = threadIdx.x >> 5, lane = threadIdx.x & 31;
    int d = blockIdx.x * 8 + w;
    int beg = g_rp[d], end = g_rp[d + 1];
    int cnt = end - beg;
    if (cnt <= 1) return;
    if (cnt <= 32) {
        // rank by counting smaller elements (eids distinct -> ranks unique)
        int v = (lane < cnt) ? g_eids[beg + lane] : 0x7fffffff;
        int rank = 0;
        #pragma unroll
        for (int j = 0; j < 32; j++) {
            int vj = __shfl_sync(0xffffffffu, v, j);
            rank += (vj < v) ? 1 : 0;
        }
        if (lane < cnt) g_eids[beg + rank] = v;
        return;
    }
    // fallback: selection sort in smem (rare: cnt > 32)
    if (cnt > 128) cnt = 128;
    for (int p = lane; p < cnt; p += 32) buf[w][p] = g_eids[beg + p];
    __syncwarp();
    for (int i = 0; i < cnt - 1; i++) {
        int bv = 0x7fffffff, bp = i;
        for (int p = i + lane; p < cnt; p += 32) {
            int v = buf[w][p];
            if (v < bv) { bv = v; bp = p; }
        }
        #pragma unroll
        for (int off = 16; off; off >>= 1) {
            int ov = __shfl_down_sync(0xffffffffu, bv, off);
            int op = __shfl_down_sync(0xffffffffu, bp, off);
            if (ov < bv) { bv = ov; bp = op; }
        }
        bv = __shfl_sync(0xffffffffu, bv, 0);
        bp = __shfl_sync(0xffffffffu, bp, 0);
        if (lane == 0) { int t = buf[w][i]; buf[w][i] = bv; buf[w][bp] = t; }
        __syncwarp();
    }
    for (int p = lane; p < cnt; p += 32) g_eids[beg + p] = buf[w][p];
}

// ---------------- fused embed: t (collapsed edge net) + h0 + W2 rearrange ----------------
__global__ void __launch_bounds__(256) k_embed(
        const float* __restrict__ ef, const float* __restrict__ nf,
        const float* __restrict__ Wa, const float* __restrict__ ba,
        const float* __restrict__ W_e2, const float* __restrict__ b_e2) {
    __shared__ float Ws[AF * H];
    __shared__ float bs[H];
    int b = blockIdx.x;
    if (b < 1250) {
        // t = relu(e_feat @ Wc + bc)
        int lane = threadIdx.x & 31;
        float wcr[BF];
        #pragma unroll
        for (int f = 0; f < BF; f++) wcr[f] = g_Wc[f * H + lane];
        float bcv = g_bc[lane];
        int w = b * 8 + (threadIdx.x >> 5);   // 0..9999
        for (int e = w; e < NE; e += 10000) {
            const float4* er = (const float4*)(ef + e * BF);
            float4 e0 = er[0], e1 = er[1], e2 = er[2], e3 = er[3];
            float a = bcv;
            a += e0.x * wcr[0]  + e0.y * wcr[1]  + e0.z * wcr[2]  + e0.w * wcr[3];
            a += e1.x * wcr[4]  + e1.y * wcr[5]  + e1.z * wcr[6]  + e1.w * wcr[7];
            a += e2.x * wcr[8]  + e2.y * wcr[9]  + e2.z * wcr[10] + e2.w * wcr[11];
            a += e3.x * wcr[12] + e3.y * wcr[13] + e3.z * wcr[14] + e3.w * wcr[15];
            g_t[e * H + lane] = fmaxf(a, 0.0f);
        }
    } else if (b < 3750) {
        // h0 = n_feat @ W_atom + b_atom
        for (int i = threadIdx.x; i < AF * H; i += 256) Ws[i] = Wa[i];
        if (threadIdx.x < H) bs[threadIdx.x] = ba[threadIdx.x];
        __syncthreads();
        int n = (b - 1250) * 8 + (threadIdx.x >> 5);
        int c = threadIdx.x & 31;
        const float* row = nf + n * AF;
        float acc = bs[c];
        #pragma unroll
        for (int f = 0; f < AF; f++) acc += __ldg(row + f) * Ws[f * H + c];
        g_h[0][n * H + c] = acc;
    } else {
        // W2 rearrange: kk=(k*32+i) -> W_e2[k, i*32+o]; rows 1024..1055 = b_e2; pad 0
        int idx = (b - 3750) * 256 + threadIdx.x;
        int kk = idx >> 5, o = idx & 31;
        float v;
        if (kk < 1024)      v = W_e2[(kk >> 5) * 1024 + (kk & 31) * 32 + o];
        else if (kk < 1056) v = b_e2[(kk - 1024) * 32 + o];
        else                v = 0.0f;
        g_W2[idx] = v;
    }
}

// ---------------- per-dst accumulated outer product ----------------
__global__ void __launch_bounds__(256) k_accum(int hs, const int* __restrict__ src) {
    const float* __restrict__ h = g_h[hs];
    int d = blockIdx.x * 8 + (threadIdx.x >> 5);
    int lane = threadIdx.x & 31;
    int beg = g_rp[d], end = g_rp[d + 1];
    ull acc2[16];
    #pragma unroll
    for (int q = 0; q < 16; q++) acc2[q] = 0ull;
    float hsum = 0.0f;
    for (int base = beg; base < end; base += 32) {
        int rem = end - base; if (rem > 32) rem = 32;
        int e_l = 0, s_l = 0;
        if (lane < rem) { e_l = __ldg(&g_eids[base + lane]); s_l = __ldg(&src[e_l]); }
        for (int p = 0; p < rem; p++) {
            int e = __shfl_sync(0xffffffffu, e_l, p);
            int s = __shfl_sync(0xffffffffu, s_l, p);
            float hv = h[s * H + lane];
            const float4* t4 = (const float4*)(g_t + e * H);
            float4 ta = t4[0], tb = t4[1], tc = t4[2], td = t4[3];
            float4 te = t4[4], tf = t4[5], tg = t4[6], th = t4[7];
            hsum += hv;
            ull h2; PK2(h2, hv, hv);
            ull tp;
            PK2(tp, ta.x, ta.y); FMA2(acc2[0],  tp, h2, acc2[0]);
            PK2(tp, ta.z, ta.w); FMA2(acc2[1],  tp, h2, acc2[1]);
            PK2(tp, tb.x, tb.y); FMA2(acc2[2],  tp, h2, acc2[2]);
            PK2(tp, tb.z, tb.w); FMA2(acc2[3],  tp, h2, acc2[3]);
            PK2(tp, tc.x, tc.y); FMA2(acc2[4],  tp, h2, acc2[4]);
            PK2(tp, tc.z, tc.w); FMA2(acc2[5],  tp, h2, acc2[5]);
            PK2(tp, td.x, td.y); FMA2(acc2[6],  tp, h2, acc2[6]);
            PK2(tp, td.z, td.w); FMA2(acc2[7],  tp, h2, acc2[7]);
            PK2(tp, te.x, te.y); FMA2(acc2[8],  tp, h2, acc2[8]);
            PK2(tp, te.z, te.w); FMA2(acc2[9],  tp, h2, acc2[9]);
            PK2(tp, tf.x, tf.y); FMA2(acc2[10], tp, h2, acc2[10]);
            PK2(tp, tf.z, tf.w); FMA2(acc2[11], tp, h2, acc2[11]);
            PK2(tp, tg.x, tg.y); FMA2(acc2[12], tp, h2, acc2[12]);
            PK2(tp, tg.z, tg.w); FMA2(acc2[13], tp, h2, acc2[13]);
            PK2(tp, th.x, th.y); FMA2(acc2[14], tp, h2, acc2[14]);
            PK2(tp, th.z, th.w); FMA2(acc2[15], tp, h2, acc2[15]);
        }
    }
    float* Pr = g_P + (long)d * KP;
    #pragma unroll
    for (int q = 0; q < 16; q++) {
        float x, y; UPK2(x, y, acc2[q]);
        Pr[(2 * q) * H + lane]     = x;
        Pr[(2 * q + 1) * H + lane] = y;
    }
    Pr[1024 + lane] = hsum;
    Pr[1056 + lane] = 0.0f;
}

// ---------------- agg GEMM: m = relu((P @ W2) * inv_deg) ----------------
__device__ __forceinline__ void gemm_load(int kb, int tid, int nb,
                                          float4* va, float4& wb0, float4& wb1) {
    #pragma unroll
    for (int i = 0; i < 8; i++) {
        int idx = i * 288 + tid;
        int node = idx >> 4, q = idx & 15;
        int gn = nb + node;
        if (gn < NN) va[i] = *(const float4*)(g_P + (long)gn * KP + kb + 4 * q);
        else         va[i] = make_float4(0.f, 0.f, 0.f, 0.f);
    }
    {
        int r = tid >> 3, c = (tid & 7) * 4;
        wb0 = *(const float4*)(g_W2 + (kb + r) * H + c);
    }
    if (tid < 224) {
        int idx = tid + 288;
        int r = idx >> 3, c = (idx & 7) * 4;
        wb1 = *(const float4*)(g_W2 + (kb + r) * H + c);
    }
}

__global__ void __launch_bounds__(288) k_gemm() {
    __shared__ float AsT[64][160];
    __shared__ float Bs[64][32];
    int tid = threadIdx.x;
    int nb = blockIdx.x * BM;
    int tx = tid & 7, ty = tid >> 3;
    ull acc[4][2];
    #pragma unroll
    for (int n = 0; n < 4; n++) { acc[n][0] = 0ull; acc[n][1] = 0ull; }

    float4 va[8];
    float4 wb0 = make_float4(0.f, 0.f, 0.f, 0.f), wb1 = wb0;
    gemm_load(0, tid, nb, va, wb0, wb1);

    #pragma unroll 1
    for (int t = 0; t < 17; t++) {
        __syncthreads();
        #pragma unroll
        for (int i = 0; i < 8; i++) {
            int idx = i * 288 + tid;
            int node = idx >> 4, q = idx & 15;
            int col = node ^ ((q & 7) << 2);
            AsT[4 * q + 0][col] = va[i].x;
            AsT[4 * q + 1][col] = va[i].y;
            AsT[4 * q + 2][col] = va[i].z;
            AsT[4 * q + 3][col] = va[i].w;
        }
        { int r = tid >> 3, c = (tid & 7) * 4; *(float4*)&Bs[r][c] = wb0; }
        if (tid < 224) { int idx = tid + 288; int r = idx >> 3, c = (idx & 7) * 4; *(float4*)&Bs[r][c] = wb1; }
        __syncthreads();
        if (t < 16) gemm_load((t + 1) * 64, tid, nb, va, wb0, wb1);
        #pragma unroll 16
        for (int kk = 0; kk < 64; kk++) {
            float4 a4 = *(const float4*)&AsT[kk][(4 * ty) ^ (((kk >> 2) & 7) << 2)];
            float4 b4 = *(const float4*)&Bs[kk][4 * tx];
            ull b01, b23, aa;
            PK2(b01, b4.x, b4.y); PK2(b23, b4.z, b4.w);
            PK2(aa, a4.x, a4.x); FMA2(acc[0][0], aa, b01, acc[0][0]); FMA2(acc[0][1], aa, b23, acc[0][1]);
            PK2(aa, a4.y, a4.y); FMA2(acc[1][0], aa, b01, acc[1][0]); FMA2(acc[1][1], aa, b23, acc[1][1]);
            PK2(aa, a4.z, a4.z); FMA2(acc[2][0], aa, b01, acc[2][0]); FMA2(acc[2][1], aa, b23, acc[2][1]);
            PK2(aa, a4.w, a4.w); FMA2(acc[3][0], aa, b01, acc[3][0]); FMA2(acc[3][1], aa, b23, acc[3][1]);
        }
    }
    #pragma unroll
    for (int n = 0; n < 4; n++) {
        int node = nb + 4 * ty + n;
        if (node < NN) {
            float iv = g_inv[node];
            float x0, x1, x2, x3;
            UPK2(x0, x1, acc[n][0]);
            UPK2(x2, x3, acc[n][1]);
            float4 o;
            o.x = fmaxf(x0 * iv, 0.0f);
            o.y = fmaxf(x1 * iv, 0.0f);
            o.z = fmaxf(x2 * iv, 0.0f);
            o.w = fmaxf(x3 * iv, 0.0f);
            *(float4*)(g_m + node * H + 4 * tx) = o;
        }
    }
}

// ---------------- GRU cell ----------------
__global__ void k_gru(int hin, int hout,
                      const float* __restrict__ Wih, const float* __restrict__ Whh,
                      const float* __restrict__ bih, const float* __restrict__ bhh) {
    __shared__ float Wis[96 * 33], Whs[96 * 33];
    __shared__ float bis[96], bhs[96];
    for (int i = threadIdx.x; i < 96 * 32; i += 256) {
        int r = i >> 5, cc = i & 31;
        Wis[r * 33 + cc] = Wih[i];
        Whs[r * 33 + cc] = Whh[i];
    }
    if (threadIdx.x < 96) { bis[threadIdx.x] = bih[threadIdx.x]; bhs[threadIdx.x] = bhh[threadIdx.x]; }
    __syncthreads();
    int n = blockIdx.x * 8 + (threadIdx.x >> 5);
    int c = threadIdx.x & 31;
    float mv = g_m[n * H + c];
    float hv = g_h[hin][n * H + c];
    float gi0 = bis[c], gi1 = bis[c + 32], gi2 = bis[c + 64];
    float gh0 = bhs[c], gh1 = bhs[c + 32], gh2 = bhs[c + 64];
    #pragma unroll
    for (int j = 0; j < H; j++) {
        float mj = __shfl_sync(0xffffffffu, mv, j);
        float hj = __shfl_sync(0xffffffffu, hv, j);
        gi0 += mj * Wis[c * 33 + j];
        gi1 += mj * Wis[(c + 32) * 33 + j];
        gi2 += mj * Wis[(c + 64) * 33 + j];
        gh0 += hj * Whs[c * 33 + j];
        gh1 += hj * Whs[(c + 32) * 33 + j];
        gh2 += hj * Whs[(c + 64) * 33 + j];
    }
    float r = 1.0f / (1.0f + __expf(-(gi0 + gh0)));
    float z = 1.0f / (1.0f + __expf(-(gi1 + gh1)));
    float nn = tanhf(gi2 + r * gh2);
    g_h[hout][n * H + c] = (1.0f - z) * nn + z * hv;
}

// ---------------- per-graph mean readout ----------------
__device__ __forceinline__ int lbound(const int* a, int n, int key) {
    int lo = 0, hi = n;
    while (lo < hi) { int mid = (lo + hi) >> 1; if (a[mid] < key) lo = mid + 1; else hi = mid; }
    return lo;
}

__global__ void k_readout(int hs, const int* __restrict__ gid, float* __restrict__ out) {
    __shared__ float red[4][32];
    int b = blockIdx.x;
    int lo = lbound(gid, NN, b), hi = lbound(gid, NN, b + 1);
    int w = threadIdx.x >> 5, lane = threadIdx.x & 31;
    const float* h = g_h[hs];
    float s = 0.0f;
    for (int n = lo + w; n < hi; n += 4) s += h[n * H + lane];
    red[w][lane] = s;
    __syncthreads();
    if (w == 0) {
        float tot = red[0][lane] + red[1][lane] + red[2][lane] + red[3][lane];
        out[b * H + lane] = tot / fmaxf((float)(hi - lo), 1.0f);
    }
}

// ---------------- launcher ----------------
extern "C" void kernel_launch(void* const* d_in, const int* in_sizes, int n_in,
                              void* d_out, int out_size) {
    const float* n_feat = (const float*)d_in[0];
    const float* e_feat = (const float*)d_in[1];
    const int*   src    = (const int*)d_in[2];
    const int*   dst    = (const int*)d_in[3];
    const int*   gid    = (const int*)d_in[4];
    const float* W_atom = (const float*)d_in[5];
    const float* b_atom = (const float*)d_in[6];
    const float* W_bond = (const float*)d_in[7];
    const float* b_bond = (const float*)d_in[8];
    const float* W_e1   = (const float*)d_in[9];
    const float* b_e1   = (const float*)d_in[10];
    const float* W_e2   = (const float*)d_in[11];
    const float* b_e2   = (const float*)d_in[12];
    const float* W_ih   = (const float*)d_in[13];
    const float* W_hh   = (const float*)d_in[14];
    const float* b_ih   = (const float*)d_in[15];
    const float* b_hh   = (const float*)d_in[16];
    float* out = (float*)d_out;

    k_hist_prep<<<1251, 256>>>(dst, W_bond, b_bond, W_e1, b_e1);
    k_scan<<<1, 1024>>>();
    k_scatter<<<1250, 256>>>(dst);
    k_embed<<<3886, 256>>>(e_feat, n_feat, W_atom, b_atom, W_e2, b_e2);
    k_sort<<<2500, 256>>>();

    for (int l = 0; l < 2; l++) {
        k_accum<<<NN / 8, 256>>>(l, src);
        k_gemm<<<(NN + BM - 1) / BM, 288>>>();
        k_gru<<<NN / 8, 256>>>(l, l + 1, W_ih, W_hh, b_ih, b_hh);
    }
    k_readout<<<NB, 128>>>(2, gid, out);
}

// round 6
// speedup vs baseline: 1.3870x; 1.0008x over previous
#include <cuda_runtime.h>
#include <math.h>

#define NN 20000
#define NE 320000
#define NB 128
#define H  32
#define AF 64
#define BF 16
#define KP 1088   // 1024 (outer product) + 32 (hsum) + 32 (zero pad)
#define BM 144    // gemm node-tile: 139 blocks < 148 SMs -> single wave

typedef unsigned long long ull;

// packed fp32x2 ops (sm_103a FFMA2 path)
#define PK2(d, x, y)     asm("mov.b64 %0, {%1, %2};" : "=l"(d) : "f"(x), "f"(y))
#define UPK2(x, y, d)    asm("mov.b64 {%0, %1}, %2;" : "=f"(x), "=f"(y) : "l"(d))
#define FMA2(d, a, b, c) asm("fma.rn.f32x2 %0, %1, %2, %3;" : "=l"(d) : "l"(a), "l"(b), "l"(c))

// ---------------- device scratch ----------------
__device__ float g_h[3][NN * H];
__device__ float g_t[NE * H];
__device__ float g_P[(long)NN * KP];
__device__ float g_m[NN * H];
__device__ float g_W2[KP * H];
__device__ float g_Wc[BF * H];     // collapsed W_bond @ W_e1
__device__ float g_bc[H];          // collapsed b_bond @ W_e1 + b_e1
__device__ float g_inv[NN];
__device__ int   g_deg[NN];        // static zero-init; re-zeroed by k_scatter each call
__device__ int   g_rp[NN + 1];
__device__ int   g_cur[NN];
__device__ int   g_eids[NE];

// ---------------- hist + edge-net weight collapse ----------------
__global__ void k_hist_prep(const int* __restrict__ dst,
                            const float* __restrict__ Wb, const float* __restrict__ bb,
                            const float* __restrict__ We1, const float* __restrict__ be1) {
    int b = blockIdx.x;
    if (b < 1250) {
        int e = b * 256 + threadIdx.x;
        atomicAdd(&g_deg[dst[e]], 1);
    } else {
        // Wc[f][o] = sum_j Wb[f][j] * We1[j][o]; bc[o] = be1[o] + sum_j bb[j]*We1[j][o]
        int tid = threadIdx.x;
        #pragma unroll
        for (int r = 0; r < 2; r++) {
            int idx = tid + r * 256;
            int f = idx >> 5, o = idx & 31;
            float acc = 0.0f;
            #pragma unroll
            for (int j = 0; j < H; j++) acc += Wb[f * H + j] * We1[j * H + o];
            g_Wc[idx] = acc;
        }
        if (tid < H) {
            float acc = be1[tid];
            #pragma unroll
            for (int j = 0; j < H; j++) acc += bb[j] * We1[j * H + tid];
            g_bc[tid] = acc;
        }
    }
}

// ---------------- scan ----------------
__global__ void k_scan() {
    __shared__ int ws[32];
    __shared__ int carry;
    int tid = threadIdx.x, lane = tid & 31, w = tid >> 5;
    if (tid == 0) carry = 0;
    __syncthreads();
    for (int base = 0; base < NN; base += 1024) {
        int i = base + tid;
        int v = (i < NN) ? g_deg[i] : 0;
        int incl = v;
        #pragma unroll
        for (int off = 1; off < 32; off <<= 1) {
            int t = __shfl_up_sync(0xffffffffu, incl, off);
            if (lane >= off) incl += t;
        }
        if (lane == 31) ws[w] = incl;
        __syncthreads();
        if (w == 0) {
            int wv = ws[lane];
            int wi = wv;
            #pragma unroll
            for (int off = 1; off < 32; off <<= 1) {
                int t = __shfl_up_sync(0xffffffffu, wi, off);
                if (lane >= off) wi += t;
            }
            ws[lane] = wi - wv;
        }
        __syncthreads();
        int excl = carry + ws[w] + incl - v;
        if (i < NN) {
            g_rp[i]  = excl;
            g_cur[i] = excl;
            g_inv[i] = 1.0f / fmaxf((float)v, 1.0f);
        }
        __syncthreads();
        if (tid == 1023) carry += ws[31] + incl;
        __syncthreads();
    }
    if (threadIdx.x == 0) g_rp[NN] = carry;
}

// ---------------- scatter (+ re-zero g_deg for next call) ----------------
__global__ void k_scatter(const int* __restrict__ dst) {
    int e = blockIdx.x * blockDim.x + threadIdx.x;
    int pos = atomicAdd(&g_cur[dst[e]], 1);
    g_eids[pos] = e;
    if (e < NN) g_deg[e] = 0;
}

// ---------------- bucket sort by edge id (deterministic accumulation order) ----------------
__global__ void k_sort() {
    __shared__ int buf[8][128];
    int w = threadIdx.x >> 5, lane = threadIdx.x & 31;
    int d = blockIdx.x * 8 + w;
    int beg = g_rp[d], end = g_rp[d + 1];
    int cnt = end - beg;
    if (cnt <= 1) return;
    if (cnt <= 32) {
        // rank by counting smaller elements (eids distinct -> ranks unique)
        int v = (lane < cnt) ? g_eids[beg + lane] : 0x7fffffff;
        int rank = 0;
        #pragma unroll
        for (int j = 0; j < 32; j++) {
            int vj = __shfl_sync(0xffffffffu, v, j);
            rank += (vj < v) ? 1 : 0;
        }
        if (lane < cnt) g_eids[beg + rank] = v;
        return;
    }
    // fallback: selection sort in smem (rare: cnt > 32)
    if (cnt > 128) cnt = 128;
    for (int p = lane; p < cnt; p += 32) buf[w][p] = g_eids[beg + p];
    __syncwarp();
    for (int i = 0; i < cnt - 1; i++) {
        int bv = 0x7fffffff, bp = i;
        for (int p = i + lane; p < cnt; p += 32) {
            int v = buf[w][p];
            if (v < bv) { bv = v; bp = p; }
        }
        #pragma unroll
        for (int off = 16; off; off >>= 1) {
            int ov = __shfl_down_sync(0xffffffffu, bv, off);
            int op = __shfl_down_sync(0xffffffffu, bp, off);
            if (ov < bv) { bv = ov; bp = op; }
        }
        bv = __shfl_sync(0xffffffffu, bv, 0);
        bp = __shfl_sync(0xffffffffu, bp, 0);
        if (lane == 0) { int t = buf[w][i]; buf[w][i] = bv; buf[w][bp] = t; }
        __syncwarp();
    }
    for (int p = lane; p < cnt; p += 32) g_eids[beg + p] = buf[w][p];
}

// ---------------- fused embed: t (collapsed edge net) + h0 + W2 rearrange ----------------
__global__ void __launch_bounds__(256) k_embed(
        const float* __restrict__ ef, const float* __restrict__ nf,
        const float* __restrict__ Wa, const float* __restrict__ ba,
        const float* __restrict__ W_e2, const float* __restrict__ b_e2) {
    __shared__ float Ws[AF * H];
    __shared__ float bs[H];
    int b = blockIdx.x;
    if (b < 1250) {
        // t = relu(e_feat @ Wc + bc)
        int lane = threadIdx.x & 31;
        float wcr[BF];
        #pragma unroll
        for (int f = 0; f < BF; f++) wcr[f] = g_Wc[f * H + lane];
        float bcv = g_bc[lane];
        int w = b * 8 + (threadIdx.x >> 5);   // 0..9999
        for (int e = w; e < NE; e += 10000) {
            const float4* er = (const float4*)(ef + e * BF);
            float4 e0 = er[0], e1 = er[1], e2 = er[2], e3 = er[3];
            float a = bcv;
            a += e0.x * wcr[0]  + e0.y * wcr[1]  + e0.z * wcr[2]  + e0.w * wcr[3];
            a += e1.x * wcr[4]  + e1.y * wcr[5]  + e1.z * wcr[6]  + e1.w * wcr[7];
            a += e2.x * wcr[8]  + e2.y * wcr[9]  + e2.z * wcr[10] + e2.w * wcr[11];
            a += e3.x * wcr[12] + e3.y * wcr[13] + e3.z * wcr[14] + e3.w * wcr[15];
            g_t[e * H + lane] = fmaxf(a, 0.0f);
        }
    } else if (b < 3750) {
        // h0 = n_feat @ W_atom + b_atom
        for (int i = threadIdx.x; i < AF * H; i += 256) Ws[i] = Wa[i];
        if (threadIdx.x < H) bs[threadIdx.x] = ba[threadIdx.x];
        __syncthreads();
        int n = (b - 1250) * 8 + (threadIdx.x >> 5);
        int c = threadIdx.x & 31;
        const float* row = nf + n * AF;
        float acc = bs[c];
        #pragma unroll
        for (int f = 0; f < AF; f++) acc += __ldg(row + f) * Ws[f * H + c];
        g_h[0][n * H + c] = acc;
    } else {
        // W2 rearrange: kk=(k*32+i) -> W_e2[k, i*32+o]; rows 1024..1055 = b_e2; pad 0
        int idx = (b - 3750) * 256 + threadIdx.x;
        int kk = idx >> 5, o = idx & 31;
        float v;
        if (kk < 1024)      v = W_e2[(kk >> 5) * 1024 + (kk & 31) * 32 + o];
        else if (kk < 1056) v = b_e2[(kk - 1024) * 32 + o];
        else                v = 0.0f;
        g_W2[idx] = v;
    }
}

// ---------------- per-dst accumulated outer product ----------------
__global__ void __launch_bounds__(256) k_accum(int hs, const int* __restrict__ src) {
    const float* __restrict__ h = g_h[hs];
    int d = blockIdx.x * 8 + (threadIdx.x >> 5);
    int lane = threadIdx.x & 31;
    int beg = g_rp[d], end = g_rp[d + 1];
    ull acc2[16];
    #pragma unroll
    for (int q = 0; q < 16; q++) acc2[q] = 0ull;
    float hsum = 0.0f;
    for (int base = beg; base < end; base += 32) {
        int rem = end - base; if (rem > 32) rem = 32;
        int e_l = 0, s_l = 0;
        if (lane < rem) { e_l = __ldg(&g_eids[base + lane]); s_l = __ldg(&src[e_l]); }
        for (int p = 0; p < rem; p++) {
            int e = __shfl_sync(0xffffffffu, e_l, p);
            int s = __shfl_sync(0xffffffffu, s_l, p);
            float hv = h[s * H + lane];
            const float4* t4 = (const float4*)(g_t + e * H);
            float4 ta = t4[0], tb = t4[1], tc = t4[2], td = t4[3];
            float4 te = t4[4], tf = t4[5], tg = t4[6], th = t4[7];
            hsum += hv;
            ull h2; PK2(h2, hv, hv);
            ull tp;
            PK2(tp, ta.x, ta.y); FMA2(acc2[0],  tp, h2, acc2[0]);
            PK2(tp, ta.z, ta.w); FMA2(acc2[1],  tp, h2, acc2[1]);
            PK2(tp, tb.x, tb.y); FMA2(acc2[2],  tp, h2, acc2[2]);
            PK2(tp, tb.z, tb.w); FMA2(acc2[3],  tp, h2, acc2[3]);
            PK2(tp, tc.x, tc.y); FMA2(acc2[4],  tp, h2, acc2[4]);
            PK2(tp, tc.z, tc.w); FMA2(acc2[5],  tp, h2, acc2[5]);
            PK2(tp, td.x, td.y); FMA2(acc2[6],  tp, h2, acc2[6]);
            PK2(tp, td.z, td.w); FMA2(acc2[7],  tp, h2, acc2[7]);
            PK2(tp, te.x, te.y); FMA2(acc2[8],  tp, h2, acc2[8]);
            PK2(tp, te.z, te.w); FMA2(acc2[9],  tp, h2, acc2[9]);
            PK2(tp, tf.x, tf.y); FMA2(acc2[10], tp, h2, acc2[10]);
            PK2(tp, tf.z, tf.w); FMA2(acc2[11], tp, h2, acc2[11]);
            PK2(tp, tg.x, tg.y); FMA2(acc2[12], tp, h2, acc2[12]);
            PK2(tp, tg.z, tg.w); FMA2(acc2[13], tp, h2, acc2[13]);
            PK2(tp, th.x, th.y); FMA2(acc2[14], tp, h2, acc2[14]);
            PK2(tp, th.z, th.w); FMA2(acc2[15], tp, h2, acc2[15]);
        }
    }
    float* Pr = g_P + (long)d * KP;
    #pragma unroll
    for (int q = 0; q < 16; q++) {
        float x, y; UPK2(x, y, acc2[q]);
        Pr[(2 * q) * H + lane]     = x;
        Pr[(2 * q + 1) * H + lane] = y;
    }
    Pr[1024 + lane] = hsum;
    Pr[1056 + lane] = 0.0f;
}

// ---------------- agg GEMM: m = relu((P @ W2) * inv_deg) ----------------
__device__ __forceinline__ void gemm_load(int kb, int tid, int nb,
                                          float4* va, float4& wb0, float4& wb1) {
    #pragma unroll
    for (int i = 0; i < 8; i++) {
        int idx = i * 288 + tid;
        int node = idx >> 4, q = idx & 15;
        int gn = nb + node;
        if (gn < NN) va[i] = *(const float4*)(g_P + (long)gn * KP + kb + 4 * q);
        else         va[i] = make_float4(0.f, 0.f, 0.f, 0.f);
    }
    {
        int r = tid >> 3, c = (tid & 7) * 4;
        wb0 = *(const float4*)(g_W2 + (kb + r) * H + c);
    }
    if (tid < 224) {
        int idx = tid + 288;
        int r = idx >> 3, c = (idx & 7) * 4;
        wb1 = *(const float4*)(g_W2 + (kb + r) * H + c);
    }
}

__global__ void __launch_bounds__(288) k_gemm() {
    __shared__ float AsT[64][160];
    __shared__ float Bs[64][32];
    int tid = threadIdx.x;
    int nb = blockIdx.x * BM;
    int tx = tid & 7, ty = tid >> 3;
    ull acc[4][2];
    #pragma unroll
    for (int n = 0; n < 4; n++) { acc[n][0] = 0ull; acc[n][1] = 0ull; }

    float4 va[8];
    float4 wb0 = make_float4(0.f, 0.f, 0.f, 0.f), wb1 = wb0;
    gemm_load(0, tid, nb, va, wb0, wb1);

    #pragma unroll 1
    for (int t = 0; t < 17; t++) {
        __syncthreads();
        #pragma unroll
        for (int i = 0; i < 8; i++) {
            int idx = i * 288 + tid;
            int node = idx >> 4, q = idx & 15;
            int col = node ^ ((q & 7) << 2);
            AsT[4 * q + 0][col] = va[i].x;
            AsT[4 * q + 1][col] = va[i].y;
            AsT[4 * q + 2][col] = va[i].z;
            AsT[4 * q + 3][col] = va[i].w;
        }
        { int r = tid >> 3, c = (tid & 7) * 4; *(float4*)&Bs[r][c] = wb0; }
        if (tid < 224) { int idx = tid + 288; int r = idx >> 3, c = (idx & 7) * 4; *(float4*)&Bs[r][c] = wb1; }
        __syncthreads();
        if (t < 16) gemm_load((t + 1) * 64, tid, nb, va, wb0, wb1);
        #pragma unroll 16
        for (int kk = 0; kk < 64; kk++) {
            float4 a4 = *(const float4*)&AsT[kk][(4 * ty) ^ (((kk >> 2) & 7) << 2)];
            float4 b4 = *(const float4*)&Bs[kk][4 * tx];
            ull b01, b23, aa;
            PK2(b01, b4.x, b4.y); PK2(b23, b4.z, b4.w);
            PK2(aa, a4.x, a4.x); FMA2(acc[0][0], aa, b01, acc[0][0]); FMA2(acc[0][1], aa, b23, acc[0][1]);
            PK2(aa, a4.y, a4.y); FMA2(acc[1][0], aa, b01, acc[1][0]); FMA2(acc[1][1], aa, b23, acc[1][1]);
            PK2(aa, a4.z, a4.z); FMA2(acc[2][0], aa, b01, acc[2][0]); FMA2(acc[2][1], aa, b23, acc[2][1]);
            PK2(aa, a4.w, a4.w); FMA2(acc[3][0], aa, b01, acc[3][0]); FMA2(acc[3][1], aa, b23, acc[3][1]);
        }
    }
    #pragma unroll
    for (int n = 0; n < 4; n++) {
        int node = nb + 4 * ty + n;
        if (node < NN) {
            float iv = g_inv[node];
            float x0, x1, x2, x3;
            UPK2(x0, x1, acc[n][0]);
            UPK2(x2, x3, acc[n][1]);
            float4 o;
            o.x = fmaxf(x0 * iv, 0.0f);
            o.y = fmaxf(x1 * iv, 0.0f);
            o.z = fmaxf(x2 * iv, 0.0f);
            o.w = fmaxf(x3 * iv, 0.0f);
            *(float4*)(g_m + node * H + 4 * tx) = o;
        }
    }
}

// ---------------- GRU cell ----------------
__global__ void k_gru(int hin, int hout,
                      const float* __restrict__ Wih, const float* __restrict__ Whh,
                      const float* __restrict__ bih, const float* __restrict__ bhh) {
    __shared__ float Wis[96 * 33], Whs[96 * 33];
    __shared__ float bis[96], bhs[96];
    for (int i = threadIdx.x; i < 96 * 32; i += 256) {
        int r = i >> 5, cc = i & 31;
        Wis[r * 33 + cc] = Wih[i];
        Whs[r * 33 + cc] = Whh[i];
    }
    if (threadIdx.x < 96) { bis[threadIdx.x] = bih[threadIdx.x]; bhs[threadIdx.x] = bhh[threadIdx.x]; }
    __syncthreads();
    int n = blockIdx.x * 8 + (threadIdx.x >> 5);
    int c = threadIdx.x & 31;
    float mv = g_m[n * H + c];
    float hv = g_h[hin][n * H + c];
    float gi0 = bis[c], gi1 = bis[c + 32], gi2 = bis[c + 64];
    float gh0 = bhs[c], gh1 = bhs[c + 32], gh2 = bhs[c + 64];
    #pragma unroll
    for (int j = 0; j < H; j++) {
        float mj = __shfl_sync(0xffffffffu, mv, j);
        float hj = __shfl_sync(0xffffffffu, hv, j);
        gi0 += mj * Wis[c * 33 + j];
        gi1 += mj * Wis[(c + 32) * 33 + j];
        gi2 += mj * Wis[(c + 64) * 33 + j];
        gh0 += hj * Whs[c * 33 + j];
        gh1 += hj * Whs[(c + 32) * 33 + j];
        gh2 += hj * Whs[(c + 64) * 33 + j];
    }
    float r = 1.0f / (1.0f + __expf(-(gi0 + gh0)));
    float z = 1.0f / (1.0f + __expf(-(gi1 + gh1)));
    float nn = tanhf(gi2 + r * gh2);
    g_h[hout][n * H + c] = (1.0f - z) * nn + z * hv;
}

// ---------------- per-graph mean readout ----------------
__device__ __forceinline__ int lbound(const int* a, int n, int key) {
    int lo = 0, hi = n;
    while (lo < hi) { int mid = (lo + hi) >> 1; if (a[mid] < key) lo = mid + 1; else hi = mid; }
    return lo;
}

__global__ void k_readout(int hs, const int* __restrict__ gid, float* __restrict__ out) {
    __shared__ float red[4][32];
    int b = blockIdx.x;
    int lo = lbound(gid, NN, b), hi = lbound(gid, NN, b + 1);
    int w = threadIdx.x >> 5, lane = threadIdx.x & 31;
    const float* h = g_h[hs];
    float s = 0.0f;
    for (int n = lo + w; n < hi; n += 4) s += h[n * H + lane];
    red[w][lane] = s;
    __syncthreads();
    if (w == 0) {
        float tot = red[0][lane] + red[1][lane] + red[2][lane] + red[3][lane];
        out[b * H + lane] = tot / fmaxf((float)(hi - lo), 1.0f);
    }
}

// ---------------- launcher ----------------
extern "C" void kernel_launch(void* const* d_in, const int* in_sizes, int n_in,
                              void* d_out, int out_size) {
    const float* n_feat = (const float*)d_in[0];
    const float* e_feat = (const float*)d_in[1];
    const int*   src    = (const int*)d_in[2];
    const int*   dst    = (const int*)d_in[3];
    const int*   gid    = (const int*)d_in[4];
    const float* W_atom = (const float*)d_in[5];
    const float* b_atom = (const float*)d_in[6];
    const float* W_bond = (const float*)d_in[7];
    const float* b_bond = (const float*)d_in[8];
    const float* W_e1   = (const float*)d_in[9];
    const float* b_e1   = (const float*)d_in[10];
    const float* W_e2   = (const float*)d_in[11];
    const float* b_e2   = (const float*)d_in[12];
    const float* W_ih   = (const float*)d_in[13];
    const float* W_hh   = (const float*)d_in[14];
    const float* b_ih   = (const float*)d_in[15];
    const float* b_hh   = (const float*)d_in[16];
    float* out = (float*)d_out;

    k_hist_prep<<<1251, 256>>>(dst, W_bond, b_bond, W_e1, b_e1);
    k_scan<<<1, 1024>>>();
    k_scatter<<<1250, 256>>>(dst);
    k_embed<<<3886, 256>>>(e_feat, n_feat, W_atom, b_atom, W_e2, b_e2);
    k_sort<<<2500, 256>>>();

    for (int l = 0; l < 2; l++) {
        k_accum<<<NN / 8, 256>>>(l, src);
        k_gemm<<<(NN + BM - 1) / BM, 288>>>();
        k_gru<<<NN / 8, 256>>>(l, l + 1, W_ih, W_hh, b_ih, b_hh);
    }
    k_readout<<<NB, 128>>>(2, gid, out);
}

// round 7
// speedup vs baseline: 1.4478x; 1.0438x over previous
#include <cuda_runtime.h>
#include <math.h>

#define NN 20000
#define NE 320000
#define NB 128
#define H  32
#define AF 64
#define BF 16
#define KP 1088
#define BM 144

typedef unsigned long long ull;

#define PK2(d, x, y)     asm("mov.b64 %0, {%1, %2};" : "=l"(d) : "f"(x), "f"(y))
#define UPK2(x, y, d)    asm("mov.b64 {%0, %1}, %2;" : "=f"(x), "=f"(y) : "l"(d))
#define FMA2(d, a, b, c) asm("fma.rn.f32x2 %0, %1, %2, %3;" : "=l"(d) : "l"(a), "l"(b), "l"(c))

__device__ float g_h[3][NN * H];
__device__ float g_t[NE * H];
__device__ float g_P[(long)NN * KP];
__device__ float g_m[NN * H];
__device__ float g_W2[KP * H];
__device__ float g_Wc[BF * H];
__device__ float g_bc[H];
__device__ float g_inv[NN];
__device__ int   g_deg[NN];
__device__ int   g_rp[NN + 1];
__device__ int   g_cur[NN];
__device__ int   g_eids[NE];

__global__ void k_hist_prep(const int* __restrict__ dst,
                            const float* __restrict__ Wb, const float* __restrict__ bb,
                            const float* __restrict__ We1, const float* __restrict__ be1) {
    int b = blockIdx.x;
    if (b < 1250) {
        int e = b * 256 + threadIdx.x;
        atomicAdd(&g_deg[dst[e]], 1);
    } else {
        int tid = threadIdx.x;
        #pragma unroll
        for (int r = 0; r < 2; r++) {
            int idx = tid + r * 256;
            int f = idx >> 5, o = idx & 31;
            float acc = 0.0f;
            #pragma unroll
            for (int j = 0; j < H; j++) acc += Wb[f * H + j] * We1[j * H + o];
            g_Wc[idx] = acc;
        }
        if (tid < H) {
            float acc = be1[tid];
            #pragma unroll
            for (int j = 0; j < H; j++) acc += bb[j] * We1[j * H + tid];
            g_bc[tid] = acc;
        }
    }
}

__global__ void k_scan() {
    __shared__ int ws[32];
    __shared__ int carry;
    int tid = threadIdx.x, lane = tid & 31, w = tid >> 5;
    if (tid == 0) carry = 0;
    __syncthreads();
    for (int base = 0; base < NN; base += 1024) {
        int i = base + tid;
        int v = (i < NN) ? g_deg[i] : 0;
        int incl = v;
        #pragma unroll
        for (int off = 1; off < 32; off <<= 1) {
            int t = __shfl_up_sync(0xffffffffu, incl, off);
            if (lane >= off) incl += t;
        }
        if (lane == 31) ws[w] = incl;
        __syncthreads();
        if (w == 0) {
            int wv = ws[lane];
            int wi = wv;
            #pragma unroll
            for (int off = 1; off < 32; off <<= 1) {
                int t = __shfl_up_sync(0xffffffffu, wi, off);
                if (lane >= off) wi += t;
            }
            ws[lane] = wi - wv;
        }
        __syncthreads();
        int excl = carry + ws[w] + incl - v;
        if (i < NN) {
            g_rp[i]  = excl;
            g_cur[i] = excl;
            g_inv[i] = 1.0f / fmaxf((float)v, 1.0f);
        }
        __syncthreads();
        if (tid == 1023) carry += ws[31] + incl;
        __syncthreads();
    }
    if (threadIdx.x == 0) g_rp[NN] = carry;
}

__global__ void k_scatter(const int* __restrict__ dst) {
    int e = blockIdx.x * blockDim.x + threadIdx.x;
    int pos = atomicAdd(&g_cur[dst[e]], 1);
    g_eids[pos] = e;
    if (e < NN) g_deg[e] = 0;
}

__global__ void k_sort() {
    __shared__ int buf[8][128];
    int w = threadIdx.x >> 5, lane = threadIdx.x & 31;
    int d = blockIdx.x * 8 + w;
    int beg = g_rp[d], end = g_rp[d + 1];
    int cnt = end - beg;
    if (cnt <= 1) return;
    if (cnt <= 32) {
        int v = (lane < cnt) ? g_eids[beg + lane] : 0x7fffffff;
        int rank = 0;
        #pragma unroll
        for (int j = 0; j < 32; j++) {
            int vj = __shfl_sync(0xffffffffu, v, j);
            rank += (vj < v) ? 1 : 0;
        }
        if (lane < cnt) g_eids[beg + rank] = v;
        return;
    }
    if (cnt > 128) cnt = 128;
    for (int p = lane; p < cnt; p += 32) buf[w][p] = g_eids[beg + p];
    __syncwarp();
    for (int i = 0; i < cnt - 1; i++) {
        int bv = 0x7fffffff, bp = i;
        for (int p = i + lane; p < cnt; p += 32) {
            int v = buf[w][p];
            if (v < bv) { bv = v; bp = p; }
        }
        #pragma unroll
        for (int off = 16; off; off >>= 1) {
            int ov = __shfl_down_sync(0xffffffffu, bv, off);
            int op = __shfl_down_sync(0xffffffffu, bp, off);
            if (ov < bv) { bv = ov; bp = op; }
        }
        bv = __shfl_sync(0xffffffffu, bv, 0);
        bp = __shfl_sync(0xffffffffu, bp, 0);
        if (lane == 0) { int t = buf[w][i]; buf[w][i] = bv; buf[w][bp] = t; }
        __syncwarp();
    }
    for (int p = lane; p < cnt; p += 32) g_eids[beg + p] = buf[w][p];
}

__global__ void __launch_bounds__(256) k_embed(
        const float* __restrict__ ef, const float* __restrict__ nf,
        const float* __restrict__ Wa, const float* __restrict__ ba,
        const float* __restrict__ W_e2, const float* __restrict__ b_e2) {
    __shared__ float Ws[AF * H];
    __shared__ float bs[H];
    int b = blockIdx.x;
    if (b < 1250) {
        // t = relu(e_feat @ Wc + bc); 32 contiguous edges per warp, 2-edge ILP
        int lane = threadIdx.x & 31;
        float wcr[BF];
        #pragma unroll
        for (int f = 0; f < BF; f++) wcr[f] = g_Wc[f * H + lane];
        float bcv = g_bc[lane];
        int ebase = (b * 8 + (threadIdx.x >> 5)) * 32;
        #pragma unroll 2
        for (int i = 0; i < 32; i += 2) {
            int ea = ebase + i, eb = ea + 1;
            const float4* ra = (const float4*)(ef + ea * BF);
            const float4* rb = (const float4*)(ef + eb * BF);
            float4 a0 = ra[0], a1 = ra[1], a2 = ra[2], a3 = ra[3];
            float4 c0 = rb[0], c1 = rb[1], c2 = rb[2], c3 = rb[3];
            float sa = bcv, sb = bcv;
            sa += a0.x * wcr[0]  + a0.y * wcr[1]  + a0.z * wcr[2]  + a0.w * wcr[3];
            sb += c0.x * wcr[0]  + c0.y * wcr[1]  + c0.z * wcr[2]  + c0.w * wcr[3];
            sa += a1.x * wcr[4]  + a1.y * wcr[5]  + a1.z * wcr[6]  + a1.w * wcr[7];
            sb += c1.x * wcr[4]  + c1.y * wcr[5]  + c1.z * wcr[6]  + c1.w * wcr[7];
            sa += a2.x * wcr[8]  + a2.y * wcr[9]  + a2.z * wcr[10] + a2.w * wcr[11];
            sb += c2.x * wcr[8]  + c2.y * wcr[9]  + c2.z * wcr[10] + c2.w * wcr[11];
            sa += a3.x * wcr[12] + a3.y * wcr[13] + a3.z * wcr[14] + a3.w * wcr[15];
            sb += c3.x * wcr[12] + c3.y * wcr[13] + c3.z * wcr[14] + c3.w * wcr[15];
            g_t[ea * H + lane] = fmaxf(sa, 0.0f);
            g_t[eb * H + lane] = fmaxf(sb, 0.0f);
        }
    } else if (b < 3750) {
        // h0 = n_feat @ W_atom + b_atom  (float4 row loads)
        for (int i = threadIdx.x; i < AF * H; i += 256) Ws[i] = Wa[i];
        if (threadIdx.x < H) bs[threadIdx.x] = ba[threadIdx.x];
        __syncthreads();
        int n = (b - 1250) * 8 + (threadIdx.x >> 5);
        int c = threadIdx.x & 31;
        const float4* r4 = (const float4*)(nf + n * AF);
        float acc = bs[c];
        #pragma unroll
        for (int q = 0; q < 16; q++) {
            float4 v = __ldg(r4 + q);
            acc += v.x * Ws[(4 * q + 0) * H + c];
            acc += v.y * Ws[(4 * q + 1) * H + c];
            acc += v.z * Ws[(4 * q + 2) * H + c];
            acc += v.w * Ws[(4 * q + 3) * H + c];
        }
        g_h[0][n * H + c] = acc;
    } else {
        int idx = (b - 3750) * 256 + threadIdx.x;
        int kk = idx >> 5, o = idx & 31;
        float v;
        if (kk < 1024)      v = W_e2[(kk >> 5) * 1024 + (kk & 31) * 32 + o];
        else if (kk < 1056) v = b_e2[(kk - 1024) * 32 + o];
        else                v = 0.0f;
        g_W2[idx] = v;
    }
}

// per-dst outer product; t rows loaded as packed ulonglong2 (no PK2 movs), 2-edge ILP
__device__ __forceinline__ void acc_edge(ull* acc2, const ull th2,
                                         const ulonglong2 t0, const ulonglong2 t1,
                                         const ulonglong2 t2, const ulonglong2 t3) {
    FMA2(acc2[0],  t0.x, th2, acc2[0]);
    FMA2(acc2[1],  t0.y, th2, acc2[1]);
    FMA2(acc2[2],  t1.x, th2, acc2[2]);
    FMA2(acc2[3],  t1.y, th2, acc2[3]);
    FMA2(acc2[4],  t2.x, th2, acc2[4]);
    FMA2(acc2[5],  t2.y, th2, acc2[5]);
    FMA2(acc2[6],  t3.x, th2, acc2[6]);
    FMA2(acc2[7],  t3.y, th2, acc2[7]);
}

__global__ void __launch_bounds__(256) k_accum(int hs, const int* __restrict__ src) {
    const float* __restrict__ h = g_h[hs];
    int d = blockIdx.x * 8 + (threadIdx.x >> 5);
    int lane = threadIdx.x & 31;
    int beg = g_rp[d], end = g_rp[d + 1];
    ull acc2[16];
    #pragma unroll
    for (int q = 0; q < 16; q++) acc2[q] = 0ull;
    float hsum = 0.0f;
    for (int base = beg; base < end; base += 32) {
        int rem = end - base; if (rem > 32) rem = 32;
        int e_l = 0, s_l = 0;
        if (lane < rem) { e_l = __ldg(&g_eids[base + lane]); s_l = __ldg(&src[e_l]); }
        int p = 0;
        for (; p + 1 < rem; p += 2) {
            int e0 = __shfl_sync(0xffffffffu, e_l, p);
            int s0 = __shfl_sync(0xffffffffu, s_l, p);
            int e1 = __shfl_sync(0xffffffffu, e_l, p + 1);
            int s1 = __shfl_sync(0xffffffffu, s_l, p + 1);
            float hv0 = h[s0 * H + lane];
            float hv1 = h[s1 * H + lane];
            const ulonglong2* ta = (const ulonglong2*)(g_t + e0 * H);
            const ulonglong2* tb = (const ulonglong2*)(g_t + e1 * H);
            ulonglong2 a0 = ta[0], a1 = ta[1], a2 = ta[2], a3 = ta[3];
            ulonglong2 a4 = ta[4], a5 = ta[5], a6 = ta[6], a7 = ta[7];
            ulonglong2 b0 = tb[0], b1 = tb[1], b2 = tb[2], b3 = tb[3];
            ulonglong2 b4 = tb[4], b5 = tb[5], b6 = tb[6], b7 = tb[7];
            hsum += hv0;
            ull h20; PK2(h20, hv0, hv0);
            acc_edge(acc2,     h20, a0, a1, a2, a3);
            acc_edge(acc2 + 8, h20, a4, a5, a6, a7);
            hsum += hv1;
            ull h21; PK2(h21, hv1, hv1);
            acc_edge(acc2,     h21, b0, b1, b2, b3);
            acc_edge(acc2 + 8, h21, b4, b5, b6, b7);
        }
        if (p < rem) {
            int e0 = __shfl_sync(0xffffffffu, e_l, p);
            int s0 = __shfl_sync(0xffffffffu, s_l, p);
            float hv0 = h[s0 * H + lane];
            const ulonglong2* ta = (const ulonglong2*)(g_t + e0 * H);
            ulonglong2 a0 = ta[0], a1 = ta[1], a2 = ta[2], a3 = ta[3];
            ulonglong2 a4 = ta[4], a5 = ta[5], a6 = ta[6], a7 = ta[7];
            hsum += hv0;
            ull h20; PK2(h20, hv0, hv0);
            acc_edge(acc2,     h20, a0, a1, a2, a3);
            acc_edge(acc2 + 8, h20, a4, a5, a6, a7);
        }
    }
    float* Pr = g_P + (long)d * KP;
    #pragma unroll
    for (int q = 0; q < 16; q++) {
        float x, y; UPK2(x, y, acc2[q]);
        Pr[(2 * q) * H + lane]     = x;
        Pr[(2 * q + 1) * H + lane] = y;
    }
    Pr[1024 + lane] = hsum;
    Pr[1056 + lane] = 0.0f;
}

__device__ __forceinline__ void gemm_load(int kb, int tid, int nb,
                                          float4* va, float4& wb0, float4& wb1) {
    #pragma unroll
    for (int i = 0; i < 8; i++) {
        int idx = i * 288 + tid;
        int node = idx >> 4, q = idx & 15;
        int gn = nb + node;
        if (gn < NN) va[i] = *(const float4*)(g_P + (long)gn * KP + kb + 4 * q);
        else         va[i] = make_float4(0.f, 0.f, 0.f, 0.f);
    }
    {
        int r = tid >> 3, c = (tid & 7) * 4;
        wb0 = *(const float4*)(g_W2 + (kb + r) * H + c);
    }
    if (tid < 224) {
        int idx = tid + 288;
        int r = idx >> 3, c = (idx & 7) * 4;
        wb1 = *(const float4*)(g_W2 + (kb + r) * H + c);
    }
}

__global__ void __launch_bounds__(288) k_gemm() {
    __shared__ float AsT[64][160];
    __shared__ float Bs[64][32];
    int tid = threadIdx.x;
    int nb = blockIdx.x * BM;
    int tx = tid & 7, ty = tid >> 3;
    ull acc[4][2];
    #pragma unroll
    for (int n = 0; n < 4; n++) { acc[n][0] = 0ull; acc[n][1] = 0ull; }

    float4 va[8];
    float4 wb0 = make_float4(0.f, 0.f, 0.f, 0.f), wb1 = wb0;
    gemm_load(0, tid, nb, va, wb0, wb1);

    #pragma unroll 1
    for (int t = 0; t < 17; t++) {
        __syncthreads();
        #pragma unroll
        for (int i = 0; i < 8; i++) {
            int idx = i * 288 + tid;
            int node = idx >> 4, q = idx & 15;
            int col = node ^ ((q & 7) << 2);
            AsT[4 * q + 0][col] = va[i].x;
            AsT[4 * q + 1][col] = va[i].y;
            AsT[4 * q + 2][col] = va[i].z;
            AsT[4 * q + 3][col] = va[i].w;
        }
        { int r = tid >> 3, c = (tid & 7) * 4; *(float4*)&Bs[r][c] = wb0; }
        if (tid < 224) { int idx = tid + 288; int r = idx >> 3, c = (idx & 7) * 4; *(float4*)&Bs[r][c] = wb1; }
        __syncthreads();
        if (t < 16) gemm_load((t + 1) * 64, tid, nb, va, wb0, wb1);
        #pragma unroll 16
        for (int kk = 0; kk < 64; kk++) {
            float4 a4 = *(const float4*)&AsT[kk][(4 * ty) ^ (((kk >> 2) & 7) << 2)];
            float4 b4 = *(const float4*)&Bs[kk][4 * tx];
            ull b01, b23, aa;
            PK2(b01, b4.x, b4.y); PK2(b23, b4.z, b4.w);
            PK2(aa, a4.x, a4.x); FMA2(acc[0][0], aa, b01, acc[0][0]); FMA2(acc[0][1], aa, b23, acc[0][1]);
            PK2(aa, a4.y, a4.y); FMA2(acc[1][0], aa, b01, acc[1][0]); FMA2(acc[1][1], aa, b23, acc[1][1]);
            PK2(aa, a4.z, a4.z); FMA2(acc[2][0], aa, b01, acc[2][0]); FMA2(acc[2][1], aa, b23, acc[2][1]);
            PK2(aa, a4.w, a4.w); FMA2(acc[3][0], aa, b01, acc[3][0]); FMA2(acc[3][1], aa, b23, acc[3][1]);
        }
    }
    #pragma unroll
    for (int n = 0; n < 4; n++) {
        int node = nb + 4 * ty + n;
        if (node < NN) {
            float iv = g_inv[node];
            float x0, x1, x2, x3;
            UPK2(x0, x1, acc[n][0]);
            UPK2(x2, x3, acc[n][1]);
            float4 o;
            o.x = fmaxf(x0 * iv, 0.0f);
            o.y = fmaxf(x1 * iv, 0.0f);
            o.z = fmaxf(x2 * iv, 0.0f);
            o.w = fmaxf(x3 * iv, 0.0f);
            *(float4*)(g_m + node * H + 4 * tx) = o;
        }
    }
}

__global__ void k_gru(int hin, int hout,
                      const float* __restrict__ Wih, const float* __restrict__ Whh,
                      const float* __restrict__ bih, const float* __restrict__ bhh) {
    __shared__ float Wis[96 * 33], Whs[96 * 33];
    __shared__ float bis[96], bhs[96];
    for (int i = threadIdx.x; i < 96 * 32; i += 256) {
        int r = i >> 5, cc = i & 31;
        Wis[r * 33 + cc] = Wih[i];
        Whs[r * 33 + cc] = Whh[i];
    }
    if (threadIdx.x < 96) { bis[threadIdx.x] = bih[threadIdx.x]; bhs[threadIdx.x] = bhh[threadIdx.x]; }
    __syncthreads();
    int n = blockIdx.x * 8 + (threadIdx.x >> 5);
    int c = threadIdx.x & 31;
    float mv = g_m[n * H + c];
    float hv = g_h[hin][n * H + c];
    float gi0 = bis[c], gi1 = bis[c + 32], gi2 = bis[c + 64];
    float gh0 = bhs[c], gh1 = bhs[c + 32], gh2 = bhs[c + 64];
    #pragma unroll
    for (int j = 0; j < H; j++) {
        float mj = __shfl_sync(0xffffffffu, mv, j);
        float hj = __shfl_sync(0xffffffffu, hv, j);
        gi0 += mj * Wis[c * 33 + j];
        gi1 += mj * Wis[(c + 32) * 33 + j];
        gi2 += mj * Wis[(c + 64) * 33 + j];
        gh0 += hj * Whs[c * 33 + j];
        gh1 += hj * Whs[(c + 32) * 33 + j];
        gh2 += hj * Whs[(c + 64) * 33 + j];
    }
    float r = 1.0f / (1.0f + __expf(-(gi0 + gh0)));
    float z = 1.0f / (1.0f + __expf(-(gi1 + gh1)));
    float nn = tanhf(gi2 + r * gh2);
    g_h[hout][n * H + c] = (1.0f - z) * nn + z * hv;
}

__device__ __forceinline__ int lbound(const int* a, int n, int key) {
    int lo = 0, hi = n;
    while (lo < hi) { int mid = (lo + hi) >> 1; if (a[mid] < key) lo = mid + 1; else hi = mid; }
    return lo;
}

__global__ void k_readout(int hs, const int* __restrict__ gid, float* __restrict__ out) {
    __shared__ float red[4][32];
    int b = blockIdx.x;
    int lo = lbound(gid, NN, b), hi = lbound(gid, NN, b + 1);
    int w = threadIdx.x >> 5, lane = threadIdx.x & 31;
    const float* h = g_h[hs];
    float s = 0.0f;
    for (int n = lo + w; n < hi; n += 4) s += h[n * H + lane];
    red[w][lane] = s;
    __syncthreads();
    if (w == 0) {
        float tot = red[0][lane] + red[1][lane] + red[2][lane] + red[3][lane];
        out[b * H + lane] = tot / fmaxf((float)(hi - lo), 1.0f);
    }
}

extern "C" void kernel_launch(void* const* d_in, const int* in_sizes, int n_in,
                              void* d_out, int out_size) {
    const float* n_feat = (const float*)d_in[0];
    const float* e_feat = (const float*)d_in[1];
    const int*   src    = (const int*)d_in[2];
    const int*   dst    = (const int*)d_in[3];
    const int*   gid    = (const int*)d_in[4];
    const float* W_bond = (const float*)d_in[7];
    const float* b_bond = (const float*)d_in[8];
    const float* W_e1   = (const float*)d_in[9];
    const float* b_e1   = (const float*)d_in[10];
    float* out = (float*)d_out;

    k_hist_prep<<<1251, 256>>>(dst, W_bond, b_bond, W_e1, b_e1);
    k_scan<<<1, 1024>>>();
    k_scatter<<<1250, 256>>>(dst);
    k_embed<<<3886, 256>>>(e_feat, n_feat, (const float*)d_in[5], (const float*)d_in[6],
                           (const float*)d_in[11], (const float*)d_in[12]);
    k_sort<<<2500, 256>>>();

    for (int l = 0; l < 2; l++) {
        k_accum<<<NN / 8, 256>>>(l, src);
        k_gemm<<<(NN + BM - 1) / BM, 288>>>();
        k_gru<<<NN / 8, 256>>>(l, l + 1, (const float*)d_in[13], (const float*)d_in[14],
                               (const float*)d_in[15], (const float*)d_in[16]);
    }
    k_readout<<<NB, 128>>>(2, gid, out);
}

// round 8
// speedup vs baseline: 1.4610x; 1.0091x over previous
#include <cuda_runtime.h>
#include <math.h>

#define NN 20000
#define NE 320000
#define NB 128
#define H  32
#define AF 64
#define BF 16
#define KP 1088
#define BM 144

typedef unsigned long long ull;

#define PK2(d, x, y)     asm("mov.b64 %0, {%1, %2};" : "=l"(d) : "f"(x), "f"(y))
#define UPK2(x, y, d)    asm("mov.b64 {%0, %1}, %2;" : "=f"(x), "=f"(y) : "l"(d))
#define FMA2(d, a, b, c) asm("fma.rn.f32x2 %0, %1, %2, %3;" : "=l"(d) : "l"(a), "l"(b), "l"(c))

__device__ float g_h[3][NN * H];
__device__ float g_t[NE * H];
__device__ float g_P[(long)NN * KP];
__device__ float g_m[NN * H];
__device__ float g_m2[NN * H];
__device__ float g_W2[KP * H];
__device__ float g_Wc[BF * H];
__device__ float g_bc[H];
__device__ float g_inv[NN];
__device__ int   g_deg[NN];
__device__ int   g_rp[NN + 1];
__device__ int   g_cur[NN];
__device__ int   g_eids[NE];

__global__ void k_hist_prep(const int* __restrict__ dst,
                            const float* __restrict__ Wb, const float* __restrict__ bb,
                            const float* __restrict__ We1, const float* __restrict__ be1) {
    int b = blockIdx.x;
    if (b < 1250) {
        int e = b * 256 + threadIdx.x;
        atomicAdd(&g_deg[dst[e]], 1);
    } else {
        int tid = threadIdx.x;
        #pragma unroll
        for (int r = 0; r < 2; r++) {
            int idx = tid + r * 256;
            int f = idx >> 5, o = idx & 31;
            float acc = 0.0f;
            #pragma unroll
            for (int j = 0; j < H; j++) acc += Wb[f * H + j] * We1[j * H + o];
            g_Wc[idx] = acc;
        }
        if (tid < H) {
            float acc = be1[tid];
            #pragma unroll
            for (int j = 0; j < H; j++) acc += bb[j] * We1[j * H + tid];
            g_bc[tid] = acc;
        }
    }
}

__global__ void k_scan() {
    __shared__ int ws[32];
    __shared__ int carry;
    int tid = threadIdx.x, lane = tid & 31, w = tid >> 5;
    if (tid == 0) carry = 0;
    __syncthreads();
    for (int base = 0; base < NN; base += 1024) {
        int i = base + tid;
        int v = (i < NN) ? g_deg[i] : 0;
        int incl = v;
        #pragma unroll
        for (int off = 1; off < 32; off <<= 1) {
            int t = __shfl_up_sync(0xffffffffu, incl, off);
            if (lane >= off) incl += t;
        }
        if (lane == 31) ws[w] = incl;
        __syncthreads();
        if (w == 0) {
            int wv = ws[lane];
            int wi = wv;
            #pragma unroll
            for (int off = 1; off < 32; off <<= 1) {
                int t = __shfl_up_sync(0xffffffffu, wi, off);
                if (lane >= off) wi += t;
            }
            ws[lane] = wi - wv;
        }
        __syncthreads();
        int excl = carry + ws[w] + incl - v;
        if (i < NN) {
            g_rp[i]  = excl;
            g_cur[i] = excl;
            g_inv[i] = 1.0f / fmaxf((float)v, 1.0f);
        }
        __syncthreads();
        if (tid == 1023) carry += ws[31] + incl;
        __syncthreads();
    }
    if (threadIdx.x == 0) g_rp[NN] = carry;
}

__global__ void k_scatter(const int* __restrict__ dst) {
    int e = blockIdx.x * blockDim.x + threadIdx.x;
    int pos = atomicAdd(&g_cur[dst[e]], 1);
    g_eids[pos] = e;
    if (e < NN) g_deg[e] = 0;
}

__global__ void k_sort() {
    __shared__ int buf[8][128];
    int w = threadIdx.x >> 5, lane = threadIdx.x & 31;
    int d = blockIdx.x * 8 + w;
    int beg = g_rp[d], end = g_rp[d + 1];
    int cnt = end - beg;
    if (cnt <= 1) return;
    if (cnt <= 32) {
        int v = (lane < cnt) ? g_eids[beg + lane] : 0x7fffffff;
        int rank = 0;
        #pragma unroll
        for (int j = 0; j < 32; j++) {
            int vj = __shfl_sync(0xffffffffu, v, j);
            rank += (vj < v) ? 1 : 0;
        }
        if (lane < cnt) g_eids[beg + rank] = v;
        return;
    }
    if (cnt > 128) cnt = 128;
    for (int p = lane; p < cnt; p += 32) buf[w][p] = g_eids[beg + p];
    __syncwarp();
    for (int i = 0; i < cnt - 1; i++) {
        int bv = 0x7fffffff, bp = i;
        for (int p = i + lane; p < cnt; p += 32) {
            int v = buf[w][p];
            if (v < bv) { bv = v; bp = p; }
        }
        #pragma unroll
        for (int off = 16; off; off >>= 1) {
            int ov = __shfl_down_sync(0xffffffffu, bv, off);
            int op = __shfl_down_sync(0xffffffffu, bp, off);
            if (ov < bv) { bv = ov; bp = op; }
        }
        bv = __shfl_sync(0xffffffffu, bv, 0);
        bp = __shfl_sync(0xffffffffu, bp, 0);
        if (lane == 0) { int t = buf[w][i]; buf[w][i] = bv; buf[w][bp] = t; }
        __syncwarp();
    }
    for (int p = lane; p < cnt; p += 32) g_eids[beg + p] = buf[w][p];
}

__global__ void __launch_bounds__(256) k_embed(
        const float* __restrict__ ef, const float* __restrict__ nf,
        const float* __restrict__ Wa, const float* __restrict__ ba,
        const float* __restrict__ W_e2, const float* __restrict__ b_e2) {
    __shared__ float Ws[AF * H];
    __shared__ float bs[H];
    int b = blockIdx.x;
    if (b < 1250) {
        int lane = threadIdx.x & 31;
        float wcr[BF];
        #pragma unroll
        for (int f = 0; f < BF; f++) wcr[f] = g_Wc[f * H + lane];
        float bcv = g_bc[lane];
        int ebase = (b * 8 + (threadIdx.x >> 5)) * 32;
        #pragma unroll 2
        for (int i = 0; i < 32; i += 2) {
            int ea = ebase + i, eb = ea + 1;
            const float4* ra = (const float4*)(ef + ea * BF);
            const float4* rb = (const float4*)(ef + eb * BF);
            float4 a0 = ra[0], a1 = ra[1], a2 = ra[2], a3 = ra[3];
            float4 c0 = rb[0], c1 = rb[1], c2 = rb[2], c3 = rb[3];
            float sa = bcv, sb = bcv;
            sa += a0.x * wcr[0]  + a0.y * wcr[1]  + a0.z * wcr[2]  + a0.w * wcr[3];
            sb += c0.x * wcr[0]  + c0.y * wcr[1]  + c0.z * wcr[2]  + c0.w * wcr[3];
            sa += a1.x * wcr[4]  + a1.y * wcr[5]  + a1.z * wcr[6]  + a1.w * wcr[7];
            sb += c1.x * wcr[4]  + c1.y * wcr[5]  + c1.z * wcr[6]  + c1.w * wcr[7];
            sa += a2.x * wcr[8]  + a2.y * wcr[9]  + a2.z * wcr[10] + a2.w * wcr[11];
            sb += c2.x * wcr[8]  + c2.y * wcr[9]  + c2.z * wcr[10] + c2.w * wcr[11];
            sa += a3.x * wcr[12] + a3.y * wcr[13] + a3.z * wcr[14] + a3.w * wcr[15];
            sb += c3.x * wcr[12] + c3.y * wcr[13] + c3.z * wcr[14] + c3.w * wcr[15];
            g_t[ea * H + lane] = fmaxf(sa, 0.0f);
            g_t[eb * H + lane] = fmaxf(sb, 0.0f);
        }
    } else if (b < 3750) {
        for (int i = threadIdx.x; i < AF * H; i += 256) Ws[i] = Wa[i];
        if (threadIdx.x < H) bs[threadIdx.x] = ba[threadIdx.x];
        __syncthreads();
        int n = (b - 1250) * 8 + (threadIdx.x >> 5);
        int c = threadIdx.x & 31;
        const float4* r4 = (const float4*)(nf + n * AF);
        float acc = bs[c];
        #pragma unroll
        for (int q = 0; q < 16; q++) {
            float4 v = __ldg(r4 + q);
            acc += v.x * Ws[(4 * q + 0) * H + c];
            acc += v.y * Ws[(4 * q + 1) * H + c];
            acc += v.z * Ws[(4 * q + 2) * H + c];
            acc += v.w * Ws[(4 * q + 3) * H + c];
        }
        g_h[0][n * H + c] = acc;
    } else {
        int idx = (b - 3750) * 256 + threadIdx.x;
        int kk = idx >> 5, o = idx & 31;
        float v;
        if (kk < 1024)      v = W_e2[(kk >> 5) * 1024 + (kk & 31) * 32 + o];
        else if (kk < 1056) v = b_e2[(kk - 1024) * 32 + o];
        else                v = 0.0f;
        g_W2[idx] = v;
    }
}

__device__ __forceinline__ void acc_edge(ull* acc2, const ull th2,
                                         const ulonglong2 t0, const ulonglong2 t1,
                                         const ulonglong2 t2, const ulonglong2 t3) {
    FMA2(acc2[0],  t0.x, th2, acc2[0]);
    FMA2(acc2[1],  t0.y, th2, acc2[1]);
    FMA2(acc2[2],  t1.x, th2, acc2[2]);
    FMA2(acc2[3],  t1.y, th2, acc2[3]);
    FMA2(acc2[4],  t2.x, th2, acc2[4]);
    FMA2(acc2[5],  t2.y, th2, acc2[5]);
    FMA2(acc2[6],  t3.x, th2, acc2[6]);
    FMA2(acc2[7],  t3.y, th2, acc2[7]);
}

__global__ void __launch_bounds__(256) k_accum(int hs, const int* __restrict__ src) {
    const float* __restrict__ h = g_h[hs];
    int d = blockIdx.x * 8 + (threadIdx.x >> 5);
    int lane = threadIdx.x & 31;
    int beg = g_rp[d], end = g_rp[d + 1];
    ull acc2[16];
    #pragma unroll
    for (int q = 0; q < 16; q++) acc2[q] = 0ull;
    float hsum = 0.0f;
    for (int base = beg; base < end; base += 32) {
        int rem = end - base; if (rem > 32) rem = 32;
        int e_l = 0, s_l = 0;
        if (lane < rem) { e_l = __ldg(&g_eids[base + lane]); s_l = __ldg(&src[e_l]); }
        int p = 0;
        for (; p + 1 < rem; p += 2) {
            int e0 = __shfl_sync(0xffffffffu, e_l, p);
            int s0 = __shfl_sync(0xffffffffu, s_l, p);
            int e1 = __shfl_sync(0xffffffffu, e_l, p + 1);
            int s1 = __shfl_sync(0xffffffffu, s_l, p + 1);
            float hv0 = h[s0 * H + lane];
            float hv1 = h[s1 * H + lane];
            const ulonglong2* ta = (const ulonglong2*)(g_t + e0 * H);
            const ulonglong2* tb = (const ulonglong2*)(g_t + e1 * H);
            ulonglong2 a0 = ta[0], a1 = ta[1], a2 = ta[2], a3 = ta[3];
            ulonglong2 a4 = ta[4], a5 = ta[5], a6 = ta[6], a7 = ta[7];
            ulonglong2 b0 = tb[0], b1 = tb[1], b2 = tb[2], b3 = tb[3];
            ulonglong2 b4 = tb[4], b5 = tb[5], b6 = tb[6], b7 = tb[7];
            hsum += hv0;
            ull h20; PK2(h20, hv0, hv0);
            acc_edge(acc2,     h20, a0, a1, a2, a3);
            acc_edge(acc2 + 8, h20, a4, a5, a6, a7);
            hsum += hv1;
            ull h21; PK2(h21, hv1, hv1);
            acc_edge(acc2,     h21, b0, b1, b2, b3);
            acc_edge(acc2 + 8, h21, b4, b5, b6, b7);
        }
        if (p < rem) {
            int e0 = __shfl_sync(0xffffffffu, e_l, p);
            int s0 = __shfl_sync(0xffffffffu, s_l, p);
            float hv0 = h[s0 * H + lane];
            const ulonglong2* ta = (const ulonglong2*)(g_t + e0 * H);
            ulonglong2 a0 = ta[0], a1 = ta[1], a2 = ta[2], a3 = ta[3];
            ulonglong2 a4 = ta[4], a5 = ta[5], a6 = ta[6], a7 = ta[7];
            hsum += hv0;
            ull h20; PK2(h20, hv0, hv0);
            acc_edge(acc2,     h20, a0, a1, a2, a3);
            acc_edge(acc2 + 8, h20, a4, a5, a6, a7);
        }
    }
    float* Pr = g_P + (long)d * KP;
    #pragma unroll
    for (int q = 0; q < 16; q++) {
        float x, y; UPK2(x, y, acc2[q]);
        Pr[(2 * q) * H + lane]     = x;
        Pr[(2 * q + 1) * H + lane] = y;
    }
    Pr[1024 + lane] = hsum;
    Pr[1056 + lane] = 0.0f;
}

// split-K GEMM: blockIdx.y = 0 -> K-tiles [0,9) -> g_m ; 1 -> [9,17) -> g_m2 (raw partials)
__device__ __forceinline__ void gemm_load(int kb, int tid, int nb,
                                          float4* va, float4& wb0, float4& wb1) {
    #pragma unroll
    for (int i = 0; i < 8; i++) {
        int idx = i * 288 + tid;
        int node = idx >> 4, q = idx & 15;
        int gn = nb + node;
        if (gn < NN) va[i] = *(const float4*)(g_P + (long)gn * KP + kb + 4 * q);
        else         va[i] = make_float4(0.f, 0.f, 0.f, 0.f);
    }
    {
        int r = tid >> 3, c = (tid & 7) * 4;
        wb0 = *(const float4*)(g_W2 + (kb + r) * H + c);
    }
    if (tid < 224) {
        int idx = tid + 288;
        int r = idx >> 3, c = (idx & 7) * 4;
        wb1 = *(const float4*)(g_W2 + (kb + r) * H + c);
    }
}

__global__ void __launch_bounds__(288) k_gemm() {
    __shared__ float AsT[64][160];
    __shared__ float Bs[64][32];
    int tid = threadIdx.x;
    int nb = blockIdx.x * BM;
    int split = blockIdx.y;
    int t0 = split ? 9 : 0;
    int nt = split ? 8 : 9;
    float* mo = split ? g_m2 : g_m;
    int tx = tid & 7, ty = tid >> 3;
    ull acc[4][2];
    #pragma unroll
    for (int n = 0; n < 4; n++) { acc[n][0] = 0ull; acc[n][1] = 0ull; }

    float4 va[8];
    float4 wb0 = make_float4(0.f, 0.f, 0.f, 0.f), wb1 = wb0;
    gemm_load(t0 * 64, tid, nb, va, wb0, wb1);

    #pragma unroll 1
    for (int t = 0; t < nt; t++) {
        __syncthreads();
        #pragma unroll
        for (int i = 0; i < 8; i++) {
            int idx = i * 288 + tid;
            int node = idx >> 4, q = idx & 15;
            int col = node ^ ((q & 7) << 2);
            AsT[4 * q + 0][col] = va[i].x;
            AsT[4 * q + 1][col] = va[i].y;
            AsT[4 * q + 2][col] = va[i].z;
            AsT[4 * q + 3][col] = va[i].w;
        }
        { int r = tid >> 3, c = (tid & 7) * 4; *(float4*)&Bs[r][c] = wb0; }
        if (tid < 224) { int idx = tid + 288; int r = idx >> 3, c = (idx & 7) * 4; *(float4*)&Bs[r][c] = wb1; }
        __syncthreads();
        if (t + 1 < nt) gemm_load((t0 + t + 1) * 64, tid, nb, va, wb0, wb1);
        #pragma unroll 16
        for (int kk = 0; kk < 64; kk++) {
            float4 a4 = *(const float4*)&AsT[kk][(4 * ty) ^ (((kk >> 2) & 7) << 2)];
            ulonglong2 b2 = *(const ulonglong2*)&Bs[kk][4 * tx];
            ull aa;
            PK2(aa, a4.x, a4.x); FMA2(acc[0][0], aa, b2.x, acc[0][0]); FMA2(acc[0][1], aa, b2.y, acc[0][1]);
            PK2(aa, a4.y, a4.y); FMA2(acc[1][0], aa, b2.x, acc[1][0]); FMA2(acc[1][1], aa, b2.y, acc[1][1]);
            PK2(aa, a4.z, a4.z); FMA2(acc[2][0], aa, b2.x, acc[2][0]); FMA2(acc[2][1], aa, b2.y, acc[2][1]);
            PK2(aa, a4.w, a4.w); FMA2(acc[3][0], aa, b2.x, acc[3][0]); FMA2(acc[3][1], aa, b2.y, acc[3][1]);
        }
    }
    #pragma unroll
    for (int n = 0; n < 4; n++) {
        int node = nb + 4 * ty + n;
        if (node < NN) {
            float x0, x1, x2, x3;
            UPK2(x0, x1, acc[n][0]);
            UPK2(x2, x3, acc[n][1]);
            *(float4*)(mo + node * H + 4 * tx) = make_float4(x0, x1, x2, x3);
        }
    }
}

__global__ void k_gru(int hin, int hout,
                      const float* __restrict__ Wih, const float* __restrict__ Whh,
                      const float* __restrict__ bih, const float* __restrict__ bhh) {
    __shared__ float Wis[96 * 33], Whs[96 * 33];
    __shared__ float bis[96], bhs[96];
    for (int i = threadIdx.x; i < 96 * 32; i += 256) {
        int r = i >> 5, cc = i & 31;
        Wis[r * 33 + cc] = Wih[i];
        Whs[r * 33 + cc] = Whh[i];
    }
    if (threadIdx.x < 96) { bis[threadIdx.x] = bih[threadIdx.x]; bhs[threadIdx.x] = bhh[threadIdx.x]; }
    __syncthreads();
    int n = blockIdx.x * 8 + (threadIdx.x >> 5);
    int c = threadIdx.x & 31;
    float mv = fmaxf((g_m[n * H + c] + g_m2[n * H + c]) * g_inv[n], 0.0f);
    float hv = g_h[hin][n * H + c];
    float gi0 = bis[c], gi1 = bis[c + 32], gi2 = bis[c + 64];
    float gh0 = bhs[c], gh1 = bhs[c + 32], gh2 = bhs[c + 64];
    #pragma unroll
    for (int j = 0; j < H; j++) {
        float mj = __shfl_sync(0xffffffffu, mv, j);
        float hj = __shfl_sync(0xffffffffu, hv, j);
        gi0 += mj * Wis[c * 33 + j];
        gi1 += mj * Wis[(c + 32) * 33 + j];
        gi2 += mj * Wis[(c + 64) * 33 + j];
        gh0 += hj * Whs[c * 33 + j];
        gh1 += hj * Whs[(c + 32) * 33 + j];
        gh2 += hj * Whs[(c + 64) * 33 + j];
    }
    float r = 1.0f / (1.0f + __expf(-(gi0 + gh0)));
    float z = 1.0f / (1.0f + __expf(-(gi1 + gh1)));
    float nn = tanhf(gi2 + r * gh2);
    g_h[hout][n * H + c] = (1.0f - z) * nn + z * hv;
}

__device__ __forceinline__ int lbound(const int* a, int n, int key) {
    int lo = 0, hi = n;
    while (lo < hi) { int mid = (lo + hi) >> 1; if (a[mid] < key) lo = mid + 1; else hi = mid; }
    return lo;
}

__global__ void k_readout(int hs, const int* __restrict__ gid, float* __restrict__ out) {
    __shared__ float red[4][32];
    int b = blockIdx.x;
    int lo = lbound(gid, NN, b), hi = lbound(gid, NN, b + 1);
    int w = threadIdx.x >> 5, lane = threadIdx.x & 31;
    const float* h = g_h[hs];
    float s = 0.0f;
    for (int n = lo + w; n < hi; n += 4) s += h[n * H + lane];
    red[w][lane] = s;
    __syncthreads();
    if (w == 0) {
        float tot = red[0][lane] + red[1][lane] + red[2][lane] + red[3][lane];
        out[b * H + lane] = tot / fmaxf((float)(hi - lo), 1.0f);
    }
}

extern "C" void kernel_launch(void* const* d_in, const int* in_sizes, int n_in,
                              void* d_out, int out_size) {
    const float* n_feat = (const float*)d_in[0];
    const float* e_feat = (const float*)d_in[1];
    const int*   src    = (const int*)d_in[2];
    const int*   dst    = (const int*)d_in[3];
    const int*   gid    = (const int*)d_in[4];
    float* out = (float*)d_out;

    k_hist_prep<<<1251, 256>>>(dst, (const float*)d_in[7], (const float*)d_in[8],
                               (const float*)d_in[9], (const float*)d_in[10]);
    k_scan<<<1, 1024>>>();
    k_scatter<<<1250, 256>>>(dst);
    k_embed<<<3886, 256>>>(e_feat, n_feat, (const float*)d_in[5], (const float*)d_in[6],
                           (const float*)d_in[11], (const float*)d_in[12]);
    k_sort<<<2500, 256>>>();

    dim3 ggrid((NN + BM - 1) / BM, 2);
    for (int l = 0; l < 2; l++) {
        k_accum<<<NN / 8, 256>>>(l, src);
        k_gemm<<<ggrid, 288>>>();
        k_gru<<<NN / 8, 256>>>(l, l + 1, (const float*)d_in[13], (const float*)d_in[14],
                               (const float*)d_in[15], (const float*)d_in[16]);
    }
    k_readout<<<NB, 128>>>(2, gid, out);
}